// round 1
// baseline (speedup 1.0000x reference)
#include <cuda_runtime.h>

#define DMODEL 1024
#define HEADS  16
#define DKH    64
#define BATCH  2
#define SEQ    2048
#define MR     (BATCH*SEQ)   // 4096 rows

// Scratch (allocation-free rule: __device__ globals)
__device__ float g_qp[MR*DMODEL];   // [B,H,S,DKH] head-split, pre-scaled by 1/8
__device__ float g_kp[MR*DMODEL];   // [B,H,S,DKH]
__device__ float g_vp[MR*DMODEL];   // [B,H,S,DKH]
__device__ float g_ao[MR*DMODEL];   // merged attention out [B,S,H*DKH]

// ---------------------------------------------------------------------------
// C = scale * A @ W^T (+bias).  A[M,DMODEL], W[DMODEL,DMODEL] both K-major.
// split=1: scatter output into head-split layout [B,H,S,DKH].
// 64x64 tile, BK=16, 256 threads, 4x4 micro-tile, reg-prefetched k-tiles.
// ---------------------------------------------------------------------------
__global__ __launch_bounds__(256) void gemm_nt(
    const float* __restrict__ A, const float* __restrict__ W,
    const float* __restrict__ bias, float* __restrict__ C,
    float scale, int split)
{
    __shared__ float As[16*64];   // [k][m]
    __shared__ float Bs[16*64];   // [k][n]
    const int tid = threadIdx.x;
    const int tx = tid & 15, ty = tid >> 4;
    const int m0 = blockIdx.y * 64, n0 = blockIdx.x * 64;
    const int lr = tid & 63;      // tile row 0..63
    const int lc = tid >> 6;      // float4 col 0..3

    const float* Ag = A + (size_t)(m0 + lr)*DMODEL + lc*4;
    const float* Wg = W + (size_t)(n0 + lr)*DMODEL + lc*4;

    float acc[4][4] = {};
    float4 av = *(const float4*)(Ag);
    float4 wv = *(const float4*)(Wg);

    for (int k0 = 0; k0 < DMODEL; k0 += 16) {
        // transpose-store: bank = lr%32 -> conflict-free (lr lane-consecutive)
        As[(lc*4+0)*64 + lr] = av.x;
        As[(lc*4+1)*64 + lr] = av.y;
        As[(lc*4+2)*64 + lr] = av.z;
        As[(lc*4+3)*64 + lr] = av.w;
        Bs[(lc*4+0)*64 + lr] = wv.x;
        Bs[(lc*4+1)*64 + lr] = wv.y;
        Bs[(lc*4+2)*64 + lr] = wv.z;
        Bs[(lc*4+3)*64 + lr] = wv.w;
        __syncthreads();
        if (k0 + 16 < DMODEL) {               // prefetch next tile into regs
            av = *(const float4*)(Ag + k0 + 16);
            wv = *(const float4*)(Wg + k0 + 16);
        }
#pragma unroll
        for (int kk = 0; kk < 16; kk++) {
            float4 a4 = *(const float4*)(As + kk*64 + ty*4);
            float4 b4 = *(const float4*)(Bs + kk*64 + tx*4);
            float a[4]  = {a4.x, a4.y, a4.z, a4.w};
            float bb[4] = {b4.x, b4.y, b4.z, b4.w};
#pragma unroll
            for (int i = 0; i < 4; i++)
#pragma unroll
                for (int j = 0; j < 4; j++)
                    acc[i][j] += a[i]*bb[j];
        }
        __syncthreads();
    }

    float bj[4] = {0.f, 0.f, 0.f, 0.f};
    if (bias) {
        float4 b4 = *(const float4*)(bias + n0 + tx*4);
        bj[0]=b4.x; bj[1]=b4.y; bj[2]=b4.z; bj[3]=b4.w;
    }
    const int n = n0 + tx*4;
#pragma unroll
    for (int i = 0; i < 4; i++) {
        int m = m0 + ty*4 + i;
        float4 r4;
        r4.x = acc[i][0]*scale + bj[0];
        r4.y = acc[i][1]*scale + bj[1];
        r4.z = acc[i][2]*scale + bj[2];
        r4.w = acc[i][3]*scale + bj[3];
        if (split) {
            int bb = m >> 11, ss = m & (SEQ-1);   // SEQ = 2048
            int hh = n >> 6,  dd = n & 63;
            *(float4*)(C + (size_t)(((bb*HEADS + hh)*SEQ) + ss)*DKH + dd) = r4;
        } else {
            *(float4*)(C + (size_t)m*DMODEL + n) = r4;
        }
    }
}

// ---------------------------------------------------------------------------
// Flash attention: one (64-query block, head, batch) per CTA. 256 threads,
// 4x4 micro-tile, online softmax. P aliases the K smem buffer (KP) so total
// static smem = 3*16KB = 48KB exactly.
// ---------------------------------------------------------------------------
__global__ __launch_bounds__(256) void flash_attn(
    const float* __restrict__ Qp, const float* __restrict__ Kp,
    const float* __restrict__ Vp, const int* __restrict__ mask,
    float* __restrict__ Out)
{
    __shared__ float Qs[64*64];   // [d][q]  (transposed)
    __shared__ float KP[64*64];   // [d][k] during QK; reused as P [q][k]
    __shared__ float Vs[64*64];   // [k][d]

    const int tid = threadIdx.x;
    const int tx = tid & 15, ty = tid >> 4;
    const int q0 = blockIdx.x * 64;
    const int h  = blockIdx.y, b = blockIdx.z;

    const float* Qg = Qp + (size_t)((b*HEADS + h)*SEQ + q0)*DKH;
    const float* Kg = Kp + (size_t)((b*HEADS + h)*SEQ)*DKH;
    const float* Vg = Vp + (size_t)((b*HEADS + h)*SEQ)*DKH;

    // Load Q tile transposed into Qs[d][q]
#pragma unroll
    for (int l = 0; l < 4; l++) {
        int idx = tid + l*256;
        int r = idx & 63, c = idx >> 6;   // c: 0..15
        float4 v = *(const float4*)(Qg + r*DKH + c*4);
        Qs[(c*4+0)*64 + r] = v.x;
        Qs[(c*4+1)*64 + r] = v.y;
        Qs[(c*4+2)*64 + r] = v.z;
        Qs[(c*4+3)*64 + r] = v.w;
    }

    float o[4][4] = {};
    float m_[4] = {-1e30f, -1e30f, -1e30f, -1e30f};
    float l_[4] = {0.f, 0.f, 0.f, 0.f};

    for (int k0 = 0; k0 < SEQ; k0 += 64) {
        // Load K transposed + V natural
#pragma unroll
        for (int l = 0; l < 4; l++) {
            int idx = tid + l*256;
            int r = idx & 63, c = idx >> 6;
            float4 kv = *(const float4*)(Kg + (size_t)(k0 + r)*DKH + c*4);
            KP[(c*4+0)*64 + r] = kv.x;
            KP[(c*4+1)*64 + r] = kv.y;
            KP[(c*4+2)*64 + r] = kv.z;
            KP[(c*4+3)*64 + r] = kv.w;
            int r2 = idx >> 4, c2 = idx & 15;
            float4 vv = *(const float4*)(Vg + (size_t)(k0 + r2)*DKH + c2*4);
            *(float4*)(Vs + r2*64 + c2*4) = vv;
        }
        __syncthreads();

        // S = Q K^T  (Q already carries 1/sqrt(64))
        float sc[4][4] = {};
#pragma unroll 8
        for (int d = 0; d < 64; d++) {
            float4 a4 = *(const float4*)(Qs + d*64 + ty*4);
            float4 k4 = *(const float4*)(KP + d*64 + tx*4);
            float a[4]  = {a4.x, a4.y, a4.z, a4.w};
            float kb[4] = {k4.x, k4.y, k4.z, k4.w};
#pragma unroll
            for (int i = 0; i < 4; i++)
#pragma unroll
                for (int j = 0; j < 4; j++)
                    sc[i][j] += a[i]*kb[j];
        }
        __syncthreads();   // everyone done reading KP-as-K

        // mask (int32 [B,S,S])
        const int mbase = (b*SEQ + (q0 + ty*4))*SEQ + k0 + tx*4;
#pragma unroll
        for (int i = 0; i < 4; i++) {
            int4 mv = *(const int4*)(mask + mbase + i*SEQ);
            if (mv.x == 0) sc[i][0] = -1e30f;
            if (mv.y == 0) sc[i][1] = -1e30f;
            if (mv.z == 0) sc[i][2] = -1e30f;
            if (mv.w == 0) sc[i][3] = -1e30f;
        }

        // online softmax (row stats reduced over the 16 tx lanes)
#pragma unroll
        for (int i = 0; i < 4; i++) {
            float rmax = fmaxf(fmaxf(sc[i][0], sc[i][1]), fmaxf(sc[i][2], sc[i][3]));
#pragma unroll
            for (int off = 1; off < 16; off <<= 1)
                rmax = fmaxf(rmax, __shfl_xor_sync(0xffffffffu, rmax, off));
            float mn    = fmaxf(m_[i], rmax);
            float alpha = __expf(m_[i] - mn);
            float rsum = 0.f;
#pragma unroll
            for (int j = 0; j < 4; j++) {
                sc[i][j] = __expf(sc[i][j] - mn);
                rsum += sc[i][j];
            }
#pragma unroll
            for (int off = 1; off < 16; off <<= 1)
                rsum += __shfl_xor_sync(0xffffffffu, rsum, off);
            l_[i] = l_[i]*alpha + rsum;
            m_[i] = mn;
#pragma unroll
            for (int j = 0; j < 4; j++) o[i][j] *= alpha;
        }

        // write P into KP as [q][k]
#pragma unroll
        for (int i = 0; i < 4; i++)
            *(float4*)(KP + (ty*4+i)*64 + tx*4) =
                make_float4(sc[i][0], sc[i][1], sc[i][2], sc[i][3]);
        __syncthreads();

        // O += P @ V
#pragma unroll 8
        for (int kk = 0; kk < 64; kk++) {
            float4 v4 = *(const float4*)(Vs + kk*64 + tx*4);
            float p0 = KP[(ty*4+0)*64 + kk];
            float p1 = KP[(ty*4+1)*64 + kk];
            float p2 = KP[(ty*4+2)*64 + kk];
            float p3 = KP[(ty*4+3)*64 + kk];
            o[0][0] += p0*v4.x; o[0][1] += p0*v4.y; o[0][2] += p0*v4.z; o[0][3] += p0*v4.w;
            o[1][0] += p1*v4.x; o[1][1] += p1*v4.y; o[1][2] += p1*v4.z; o[1][3] += p1*v4.w;
            o[2][0] += p2*v4.x; o[2][1] += p2*v4.y; o[2][2] += p2*v4.z; o[2][3] += p2*v4.w;
            o[3][0] += p3*v4.x; o[3][1] += p3*v4.y; o[3][2] += p3*v4.z; o[3][3] += p3*v4.w;
        }
        __syncthreads();
    }

    // normalize + write merged layout [B,S, h*64+d]
#pragma unroll
    for (int i = 0; i < 4; i++) {
        float inv = 1.0f / l_[i];
        float4 r4 = make_float4(o[i][0]*inv, o[i][1]*inv, o[i][2]*inv, o[i][3]*inv);
        *(float4*)(Out + (size_t)(b*SEQ + q0 + ty*4 + i)*DMODEL + h*DKH + tx*4) = r4;
    }
}

// ---------------------------------------------------------------------------
extern "C" void kernel_launch(void* const* d_in, const int* in_sizes, int n_in,
                              void* d_out, int out_size)
{
    const float* q  = (const float*)d_in[0];
    const float* k  = (const float*)d_in[1];
    const float* v  = (const float*)d_in[2];
    const int*   mk = (const int*)  d_in[3];
    const float* wq = (const float*)d_in[4];
    const float* wk = (const float*)d_in[5];
    const float* wv = (const float*)d_in[6];
    const float* wo = (const float*)d_in[7];
    const float* bo = (const float*)d_in[8];
    float* out = (float*)d_out;

    float *qp, *kp, *vp, *ao;
    cudaGetSymbolAddress((void**)&qp, g_qp);
    cudaGetSymbolAddress((void**)&kp, g_kp);
    cudaGetSymbolAddress((void**)&vp, g_vp);
    cudaGetSymbolAddress((void**)&ao, g_ao);

    dim3 gg(DMODEL/64, MR/64);   // (16, 64)
    gemm_nt<<<gg, 256>>>(q, wq, nullptr, qp, 0.125f, 1);   // 1/sqrt(64) folded
    gemm_nt<<<gg, 256>>>(k, wk, nullptr, kp, 1.0f, 1);
    gemm_nt<<<gg, 256>>>(v, wv, nullptr, vp, 1.0f, 1);
    flash_attn<<<dim3(SEQ/64, HEADS, BATCH), 256>>>(qp, kp, vp, mk, ao);
    gemm_nt<<<gg, 256>>>(ao, wo, bo, out, 1.0f, 0);
}

// round 2
// speedup vs baseline: 5.0908x; 5.0908x over previous
#include <cuda_runtime.h>

#define DMODEL 1024
#define HEADS  16
#define DKH    64
#define BATCH  2
#define SEQ    2048
#define MR     (BATCH*SEQ)   // 4096 rows

// Scratch (allocation-free rule: __device__ globals)
__device__ float g_qp[MR*DMODEL];   // [B,H,S,DKH] head-split, pre-scaled by 1/8
__device__ float g_kp[MR*DMODEL];   // [B,H,S,DKH]
__device__ float g_vp[MR*DMODEL];   // [B,H,S,DKH]
__device__ float g_ao[MR*DMODEL];   // merged attention out [B,S,H*DKH]

__device__ __forceinline__ unsigned cvt_tf32(float x) {
    unsigned u; asm("cvt.rna.tf32.f32 %0, %1;" : "=r"(u) : "f"(x)); return u;
}
__device__ __forceinline__ uint4 cvt4(float4 v) {
    return make_uint4(cvt_tf32(v.x), cvt_tf32(v.y), cvt_tf32(v.z), cvt_tf32(v.w));
}
// D = A(16x8,row) * B(8x8,col) + D, tf32 in, fp32 accum
__device__ __forceinline__ void mma8(float* c, const unsigned* a, const unsigned* b) {
    asm volatile("mma.sync.aligned.m16n8k8.row.col.f32.tf32.tf32.f32 "
        "{%0,%1,%2,%3}, {%4,%5,%6,%7}, {%8,%9}, {%0,%1,%2,%3};"
        : "+f"(c[0]), "+f"(c[1]), "+f"(c[2]), "+f"(c[3])
        : "r"(a[0]), "r"(a[1]), "r"(a[2]), "r"(a[3]), "r"(b[0]), "r"(b[1]));
}

// ---------------------------------------------------------------------------
// C = scale * A @ W^T (+bias).  A[M,1024], W[1024,1024] row-major (K-major).
// CTA tile 128x64, Kt=32, 256 threads / 8 warps, warp tile 32x32 (2x4 frags).
// split=1: scatter C into head-split [B,H,S,DKH].
// ---------------------------------------------------------------------------
#define AST 36
__global__ __launch_bounds__(256) void gemm_tf32(
    const float* __restrict__ A, const float* __restrict__ W,
    const float* __restrict__ bias, float* __restrict__ C,
    float scale, int split)
{
    __shared__ unsigned As[128*AST];
    __shared__ unsigned Bs[64*AST];
    const int tid = threadIdx.x, lane = tid & 31;
    const int g = lane >> 2, t = lane & 3;
    const int wid = tid >> 5;
    const int wm = (wid & 3) * 32, wn = (wid >> 2) * 32;
    const int m0 = blockIdx.y * 128, n0 = blockIdx.x * 64;

    int arow[4], akq[4], brow[2], bkq[2];
#pragma unroll
    for (int l = 0; l < 4; l++) { int lin = tid + l*256; arow[l] = lin >> 3; akq[l] = (lin & 7)*4; }
#pragma unroll
    for (int l = 0; l < 2; l++) { int lin = tid + l*256; brow[l] = lin >> 3; bkq[l] = (lin & 7)*4; }

    const float* Ag = A + (size_t)m0 * DMODEL;
    const float* Wg = W + (size_t)n0 * DMODEL;

    float4 ra[4], rb[2];
#pragma unroll
    for (int l = 0; l < 4; l++) ra[l] = *(const float4*)(Ag + (size_t)arow[l]*DMODEL + akq[l]);
#pragma unroll
    for (int l = 0; l < 2; l++) rb[l] = *(const float4*)(Wg + (size_t)brow[l]*DMODEL + bkq[l]);

    float acc[2][4][4] = {};

    for (int k0 = 0; k0 < DMODEL; k0 += 32) {
#pragma unroll
        for (int l = 0; l < 4; l++) *(uint4*)&As[arow[l]*AST + akq[l]] = cvt4(ra[l]);
#pragma unroll
        for (int l = 0; l < 2; l++) *(uint4*)&Bs[brow[l]*AST + bkq[l]] = cvt4(rb[l]);
        __syncthreads();
        if (k0 + 32 < DMODEL) {
#pragma unroll
            for (int l = 0; l < 4; l++) ra[l] = *(const float4*)(Ag + (size_t)arow[l]*DMODEL + k0 + 32 + akq[l]);
#pragma unroll
            for (int l = 0; l < 2; l++) rb[l] = *(const float4*)(Wg + (size_t)brow[l]*DMODEL + k0 + 32 + bkq[l]);
        }
#pragma unroll
        for (int ks = 0; ks < 4; ks++) {
            const int k = ks * 8;
            unsigned af[2][4], bf[4][2];
#pragma unroll
            for (int fm = 0; fm < 2; fm++) {
                int r = wm + fm*16 + g;
                af[fm][0] = As[r*AST + k + t];
                af[fm][1] = As[(r+8)*AST + k + t];
                af[fm][2] = As[r*AST + k + t + 4];
                af[fm][3] = As[(r+8)*AST + k + t + 4];
            }
#pragma unroll
            for (int fn = 0; fn < 4; fn++) {
                int c = wn + fn*8 + g;
                bf[fn][0] = Bs[c*AST + k + t];
                bf[fn][1] = Bs[c*AST + k + t + 4];
            }
#pragma unroll
            for (int fm = 0; fm < 2; fm++)
#pragma unroll
                for (int fn = 0; fn < 4; fn++) mma8(acc[fm][fn], af[fm], bf[fn]);
        }
        __syncthreads();
    }

#pragma unroll
    for (int fn = 0; fn < 4; fn++) {
        int n = n0 + wn + fn*8 + 2*t;
        float b0 = 0.f, b1 = 0.f;
        if (bias) { b0 = bias[n]; b1 = bias[n+1]; }
#pragma unroll
        for (int fm = 0; fm < 2; fm++) {
#pragma unroll
            for (int rr = 0; rr < 2; rr++) {
                int m = m0 + wm + fm*16 + g + rr*8;
                float2 v;
                v.x = acc[fm][fn][rr*2]   * scale + b0;
                v.y = acc[fm][fn][rr*2+1] * scale + b1;
                if (split) {
                    int bb = m >> 11, ss = m & (SEQ-1);
                    int hh = n >> 6,  dd = n & 63;
                    *(float2*)(C + (size_t)(((bb*HEADS + hh)*SEQ) + ss)*DKH + dd) = v;
                } else {
                    *(float2*)(C + (size_t)m*DMODEL + n) = v;
                }
            }
        }
    }
}

// ---------------------------------------------------------------------------
// Flash attention, tf32 mma. Br=64 (4 warps x 16 q-rows), Bc=64, online softmax
// fully warp-local. P aliases the K smem buffer. Dynamic smem: 3 * 64*68 * 4B.
// ---------------------------------------------------------------------------
#define FST 68
__global__ __launch_bounds__(128) void flash_tf32(
    const float* __restrict__ Qp, const float* __restrict__ Kp,
    const float* __restrict__ Vp, const int* __restrict__ mask,
    float* __restrict__ Out)
{
    extern __shared__ unsigned sm_[];
    unsigned* Qs  = sm_;                 // [q][d]   64x68
    unsigned* KPs = sm_ + 64*FST;        // [kpos][d] during S; [q][kpos] as P
    unsigned* Vs  = sm_ + 2*64*FST;      // [kpos][d]

    const int tid = threadIdx.x, lane = tid & 31;
    const int g = lane >> 2, t = lane & 3, wid = tid >> 5;
    const int q0 = blockIdx.x * 64, h = blockIdx.y, b = blockIdx.z;
    const int qw = wid * 16;

    const float* Qg = Qp + (size_t)((b*HEADS + h)*SEQ + q0)*DKH;
    const float* Kg = Kp + (size_t)((b*HEADS + h)*SEQ)*DKH;
    const float* Vg = Vp + (size_t)((b*HEADS + h)*SEQ)*DKH;

#pragma unroll
    for (int l = 0; l < 8; l++) {
        int lin = tid + l*128; int r = lin >> 4, c = (lin & 15)*4;
        *(uint4*)&Qs[r*FST + c] = cvt4(*(const float4*)(Qg + (size_t)r*DKH + c));
    }

    float o[8][4] = {};
    float m_[2] = {-1e30f, -1e30f};
    float l_[2] = {0.f, 0.f};

    for (int k0 = 0; k0 < SEQ; k0 += 64) {
        __syncthreads();   // prior tile's reads of KPs/Vs complete
#pragma unroll
        for (int l = 0; l < 8; l++) {
            int lin = tid + l*128; int r = lin >> 4, c = (lin & 15)*4;
            *(uint4*)&KPs[r*FST + c] = cvt4(*(const float4*)(Kg + (size_t)(k0+r)*DKH + c));
            *(uint4*)&Vs [r*FST + c] = cvt4(*(const float4*)(Vg + (size_t)(k0+r)*DKH + c));
        }
        int2 mk2[2][8];
#pragma unroll
        for (int rr = 0; rr < 2; rr++) {
            const int* mp = mask + (size_t)(b*SEQ + q0 + qw + g + rr*8)*SEQ + k0 + 2*t;
#pragma unroll
            for (int fn = 0; fn < 8; fn++) mk2[rr][fn] = *(const int2*)(mp + fn*8);
        }
        __syncthreads();

        // S = Q K^T (Q pre-scaled by 1/8)
        float sc[8][4] = {};
#pragma unroll
        for (int ks = 0; ks < 8; ks++) {
            const int k = ks*8, r = qw + g;
            unsigned aq[4];
            aq[0] = Qs[r*FST + k + t];     aq[1] = Qs[(r+8)*FST + k + t];
            aq[2] = Qs[r*FST + k + t + 4]; aq[3] = Qs[(r+8)*FST + k + t + 4];
#pragma unroll
            for (int fn = 0; fn < 8; fn++) {
                unsigned bk[2];
                int c = fn*8 + g;
                bk[0] = KPs[c*FST + k + t];
                bk[1] = KPs[c*FST + k + t + 4];
                mma8(sc[fn], aq, bk);
            }
        }

        // mask + online softmax (rows g and g+8 of this warp's 16-row block)
#pragma unroll
        for (int rr = 0; rr < 2; rr++) {
#pragma unroll
            for (int fn = 0; fn < 8; fn++) {
                if (mk2[rr][fn].x == 0) sc[fn][rr*2]   = -1e30f;
                if (mk2[rr][fn].y == 0) sc[fn][rr*2+1] = -1e30f;
            }
            float rmax = -1e30f;
#pragma unroll
            for (int fn = 0; fn < 8; fn++)
                rmax = fmaxf(rmax, fmaxf(sc[fn][rr*2], sc[fn][rr*2+1]));
            rmax = fmaxf(rmax, __shfl_xor_sync(0xffffffffu, rmax, 1));
            rmax = fmaxf(rmax, __shfl_xor_sync(0xffffffffu, rmax, 2));
            float mn = fmaxf(m_[rr], rmax);
            float alpha = __expf(m_[rr] - mn);
            float rsum = 0.f;
#pragma unroll
            for (int fn = 0; fn < 8; fn++) {
                sc[fn][rr*2]   = __expf(sc[fn][rr*2]   - mn);
                sc[fn][rr*2+1] = __expf(sc[fn][rr*2+1] - mn);
                rsum += sc[fn][rr*2] + sc[fn][rr*2+1];
            }
            rsum += __shfl_xor_sync(0xffffffffu, rsum, 1);
            rsum += __shfl_xor_sync(0xffffffffu, rsum, 2);
            l_[rr] = l_[rr]*alpha + rsum;
            m_[rr] = mn;
#pragma unroll
            for (int fn = 0; fn < 8; fn++) { o[fn][rr*2] *= alpha; o[fn][rr*2+1] *= alpha; }
        }
        __syncthreads();   // everyone done reading KPs as K

        // write P as [q][kpos] (tf32) into KPs — own rows only
#pragma unroll
        for (int rr = 0; rr < 2; rr++) {
            int r = qw + g + rr*8;
#pragma unroll
            for (int fn = 0; fn < 8; fn++) {
                uint2 u;
                u.x = cvt_tf32(sc[fn][rr*2]);
                u.y = cvt_tf32(sc[fn][rr*2+1]);
                *(uint2*)&KPs[r*FST + fn*8 + 2*t] = u;
            }
        }
        __syncwarp();

        // O += P @ V
#pragma unroll
        for (int ks = 0; ks < 8; ks++) {
            const int k = ks*8, r = qw + g;
            unsigned ap[4];
            ap[0] = KPs[r*FST + k + t];     ap[1] = KPs[(r+8)*FST + k + t];
            ap[2] = KPs[r*FST + k + t + 4]; ap[3] = KPs[(r+8)*FST + k + t + 4];
#pragma unroll
            for (int fn = 0; fn < 8; fn++) {
                unsigned bv[2];
                bv[0] = Vs[(k+t)*FST   + fn*8 + g];
                bv[1] = Vs[(k+t+4)*FST + fn*8 + g];
                mma8(o[fn], ap, bv);
            }
        }
    }

    // normalize + write merged [B,S, h*64+d]
#pragma unroll
    for (int rr = 0; rr < 2; rr++) {
        float inv = 1.0f / l_[rr];
        int row = q0 + qw + g + rr*8;
        float* op = Out + (size_t)(b*SEQ + row)*DMODEL + h*DKH + 2*t;
#pragma unroll
        for (int fn = 0; fn < 8; fn++) {
            float2 v;
            v.x = o[fn][rr*2]   * inv;
            v.y = o[fn][rr*2+1] * inv;
            *(float2*)(op + fn*8) = v;
        }
    }
}

// ---------------------------------------------------------------------------
extern "C" void kernel_launch(void* const* d_in, const int* in_sizes, int n_in,
                              void* d_out, int out_size)
{
    const float* q  = (const float*)d_in[0];
    const float* k  = (const float*)d_in[1];
    const float* v  = (const float*)d_in[2];
    const int*   mk = (const int*)  d_in[3];
    const float* wq = (const float*)d_in[4];
    const float* wk = (const float*)d_in[5];
    const float* wv = (const float*)d_in[6];
    const float* wo = (const float*)d_in[7];
    const float* bo = (const float*)d_in[8];
    float* out = (float*)d_out;

    float *qp, *kp, *vp, *ao;
    cudaGetSymbolAddress((void**)&qp, g_qp);
    cudaGetSymbolAddress((void**)&kp, g_kp);
    cudaGetSymbolAddress((void**)&vp, g_vp);
    cudaGetSymbolAddress((void**)&ao, g_ao);

    const int flash_smem = 3 * 64 * FST * 4;   // 52224 B
    cudaFuncSetAttribute(flash_tf32, cudaFuncAttributeMaxDynamicSharedMemorySize, flash_smem);

    dim3 gg(DMODEL/64, MR/128);   // (16, 32)
    gemm_tf32<<<gg, 256>>>(q, wq, nullptr, qp, 0.125f, 1);   // 1/sqrt(64) folded
    gemm_tf32<<<gg, 256>>>(k, wk, nullptr, kp, 1.0f, 1);
    gemm_tf32<<<gg, 256>>>(v, wv, nullptr, vp, 1.0f, 1);
    flash_tf32<<<dim3(SEQ/64, HEADS, BATCH), 128, flash_smem>>>(qp, kp, vp, mk, ao);
    gemm_tf32<<<gg, 256>>>(ao, wo, bo, out, 1.0f, 0);
}

// round 3
// speedup vs baseline: 5.5309x; 1.0865x over previous
#include <cuda_runtime.h>

#define DMODEL 1024
#define HEADS  16
#define DKH    64
#define BATCH  2
#define SEQ    2048
#define MR     (BATCH*SEQ)   // 4096 rows

// Scratch (allocation-free rule: __device__ globals)
__device__ float g_qp[MR*DMODEL];   // [B,H,S,DKH] head-split, pre-scaled by 1/8
__device__ float g_kp[MR*DMODEL];   // [B,H,S,DKH]
__device__ float g_vp[MR*DMODEL];   // [B,H,S,DKH]
__device__ float g_ao[MR*DMODEL];   // merged attention out [B,S,H*DKH]

__device__ __forceinline__ unsigned cvt_tf32(float x) {
    unsigned u; asm("cvt.rna.tf32.f32 %0, %1;" : "=r"(u) : "f"(x)); return u;
}
__device__ __forceinline__ uint4 cvt4(float4 v) {
    return make_uint4(cvt_tf32(v.x), cvt_tf32(v.y), cvt_tf32(v.z), cvt_tf32(v.w));
}
// D = A(16x8,row) * B(8x8,col) + D, tf32 in, fp32 accum
__device__ __forceinline__ void mma8(float* c, const unsigned* a, const unsigned* b) {
    asm volatile("mma.sync.aligned.m16n8k8.row.col.f32.tf32.tf32.f32 "
        "{%0,%1,%2,%3}, {%4,%5,%6,%7}, {%8,%9}, {%0,%1,%2,%3};"
        : "+f"(c[0]), "+f"(c[1]), "+f"(c[2]), "+f"(c[3])
        : "r"(a[0]), "r"(a[1]), "r"(a[2]), "r"(a[3]), "r"(b[0]), "r"(b[1]));
}

// ---------------------------------------------------------------------------
// C = scale * A @ W^T (+bias).  A[M,1024], W[1024,1024] row-major (K-major).
// CTA 128x128, 4 warps (2x2), warp tile 64x64 (4x8 m16n8k8 frags), Kt=16.
// 1.0 LDS-wavefront per MMA -> smem/tensor balanced.
// split=1: scatter C into head-split [B,H,S,DKH].
// ---------------------------------------------------------------------------
#define GST 20
__global__ __launch_bounds__(128, 1) void gemm_tf32(
    const float* __restrict__ A, const float* __restrict__ W,
    const float* __restrict__ bias, float* __restrict__ C,
    float scale, int split)
{
    __shared__ unsigned As[128*GST];
    __shared__ unsigned Bs[128*GST];
    const int tid = threadIdx.x, lane = tid & 31;
    const int g = lane >> 2, t = lane & 3, wid = tid >> 5;
    const int wm = (wid & 1) * 64, wn = (wid >> 1) * 64;
    const int m0 = blockIdx.y * 128, n0 = blockIdx.x * 128;

    // global-load mapping: 128x16 tile = 512 float4, 4 per thread
    int grow[4], gcol[4];
#pragma unroll
    for (int l = 0; l < 4; l++) {
        int f = tid + l*128;
        grow[l] = f >> 2; gcol[l] = (f & 3) * 4;
    }

    const float* Ag = A + (size_t)m0 * DMODEL;
    const float* Wg = W + (size_t)n0 * DMODEL;

    float4 ra[4], rb[4];
#pragma unroll
    for (int l = 0; l < 4; l++) {
        ra[l] = *(const float4*)(Ag + (size_t)grow[l]*DMODEL + gcol[l]);
        rb[l] = *(const float4*)(Wg + (size_t)grow[l]*DMODEL + gcol[l]);
    }

    float acc[4][8][4] = {};

    for (int k0 = 0; k0 < DMODEL; k0 += 16) {
#pragma unroll
        for (int l = 0; l < 4; l++) {
            *(uint4*)&As[grow[l]*GST + gcol[l]] = cvt4(ra[l]);
            *(uint4*)&Bs[grow[l]*GST + gcol[l]] = cvt4(rb[l]);
        }
        __syncthreads();
        if (k0 + 16 < DMODEL) {
#pragma unroll
            for (int l = 0; l < 4; l++) {
                ra[l] = *(const float4*)(Ag + (size_t)grow[l]*DMODEL + k0 + 16 + gcol[l]);
                rb[l] = *(const float4*)(Wg + (size_t)grow[l]*DMODEL + k0 + 16 + gcol[l]);
            }
        }
#pragma unroll
        for (int ks = 0; ks < 2; ks++) {
            const int k = ks * 8;
            unsigned af[4][4], bf[8][2];
#pragma unroll
            for (int fm = 0; fm < 4; fm++) {
                int r = wm + fm*16 + g;
                af[fm][0] = As[r*GST + k + t];
                af[fm][1] = As[(r+8)*GST + k + t];
                af[fm][2] = As[r*GST + k + t + 4];
                af[fm][3] = As[(r+8)*GST + k + t + 4];
            }
#pragma unroll
            for (int fn = 0; fn < 8; fn++) {
                int c = wn + fn*8 + g;
                bf[fn][0] = Bs[c*GST + k + t];
                bf[fn][1] = Bs[c*GST + k + t + 4];
            }
#pragma unroll
            for (int fm = 0; fm < 4; fm++)
#pragma unroll
                for (int fn = 0; fn < 8; fn++) mma8(acc[fm][fn], af[fm], bf[fn]);
        }
        __syncthreads();
    }

#pragma unroll
    for (int fn = 0; fn < 8; fn++) {
        int n = n0 + wn + fn*8 + 2*t;
        float b0 = 0.f, b1 = 0.f;
        if (bias) { b0 = bias[n]; b1 = bias[n+1]; }
#pragma unroll
        for (int fm = 0; fm < 4; fm++) {
#pragma unroll
            for (int rr = 0; rr < 2; rr++) {
                int m = m0 + wm + fm*16 + g + rr*8;
                float2 v;
                v.x = acc[fm][fn][rr*2]   * scale + b0;
                v.y = acc[fm][fn][rr*2+1] * scale + b1;
                if (split) {
                    int bb = m >> 11, ss = m & (SEQ-1);
                    int hh = n >> 6,  dd = n & 63;
                    *(float2*)(C + (size_t)(((bb*HEADS + hh)*SEQ) + ss)*DKH + dd) = v;
                } else {
                    *(float2*)(C + (size_t)m*DMODEL + n) = v;
                }
            }
        }
    }
}

// ---------------------------------------------------------------------------
// Flash attention, tf32 mma. Br=64 (4 warps x 16 q-rows), Bc=64.
// Q fragments register-resident. K double-buffered (stride 68), V
// double-buffered (stride 72, conflict-free frag reads), dedicated P buffer.
// One __syncthreads per tile; K/V prefetched to regs during S-MMA.
// ---------------------------------------------------------------------------
#define FST 68
#define VST 72
__global__ __launch_bounds__(128, 1) void flash_tf32(
    const float* __restrict__ Qp, const float* __restrict__ Kp,
    const float* __restrict__ Vp, const int* __restrict__ mask,
    float* __restrict__ Out)
{
    extern __shared__ unsigned sm_[];
    unsigned* Ks = sm_;                         // 2 x [64][FST]
    unsigned* Vs = sm_ + 2*64*FST;              // 2 x [64][VST]
    unsigned* Ps = sm_ + 2*64*FST + 2*64*VST;   // [64][FST]; also Q staging

    const int tid = threadIdx.x, lane = tid & 31;
    const int g = lane >> 2, t = lane & 3, wid = tid >> 5;
    const int q0 = blockIdx.x * 64, h = blockIdx.y, b = blockIdx.z;
    const int qw = wid * 16;

    const float* Qg = Qp + (size_t)((b*HEADS + h)*SEQ + q0)*DKH;
    const float* Kg = Kp + (size_t)((b*HEADS + h)*SEQ)*DKH;
    const float* Vg = Vp + (size_t)((b*HEADS + h)*SEQ)*DKH;

    // Stage Q (via Ps) + first K/V tile
#pragma unroll
    for (int l = 0; l < 8; l++) {
        int lin = tid + l*128; int r = lin >> 4, c = (lin & 15)*4;
        *(uint4*)&Ps[r*FST + c] = cvt4(*(const float4*)(Qg + (size_t)r*DKH + c));
        *(uint4*)&Ks[r*FST + c] = cvt4(*(const float4*)(Kg + (size_t)r*DKH + c));
        *(uint4*)&Vs[r*VST + c] = cvt4(*(const float4*)(Vg + (size_t)r*DKH + c));
    }
    __syncthreads();

    // Q fragments -> registers (own warp rows only)
    unsigned aq[8][4];
#pragma unroll
    for (int ks = 0; ks < 8; ks++) {
        const int k = ks*8, r = qw + g;
        aq[ks][0] = Ps[r*FST + k + t];     aq[ks][1] = Ps[(r+8)*FST + k + t];
        aq[ks][2] = Ps[r*FST + k + t + 4]; aq[ks][3] = Ps[(r+8)*FST + k + t + 4];
    }

    float o[8][4] = {};
    float m_[2] = {-1e30f, -1e30f};
    float l_[2] = {0.f, 0.f};

    for (int k0 = 0; k0 < SEQ; k0 += 64) {
        const int buf = (k0 >> 6) & 1;
        unsigned* Kb = Ks + buf*64*FST;
        unsigned* Vb = Vs + buf*64*VST;
        const bool nxt = (k0 + 64 < SEQ);

        // prefetch next K/V tile into regs (latency hidden by S-MMA)
        float4 rk[4], rv[4];
        if (nxt) {
#pragma unroll
            for (int l = 0; l < 4; l++) {
                int lin = tid + l*128; int r = lin >> 3, c = (lin & 7)*4;  // wait remapped below
            }
#pragma unroll
            for (int l = 0; l < 4; l++) {
                int lin = tid + l*128; int r = (lin >> 4) + ((l & 2) ? 0 : 0), c = (lin & 15)*4;
                (void)r; (void)c;
            }
            // 8 float4 per (K,V) tile over 128 threads * 4: rows lin>>4 covers 0..31 for l<4.
            // Use l 0..3 for rows 0..31 and reuse same regs twice is wrong; instead:
            // 4 regs each cover half-tile; second half loaded after first STS below.
#pragma unroll
            for (int l = 0; l < 4; l++) {
                int lin = tid + l*128; int r = lin >> 4, c = (lin & 15)*4;
                rk[l] = *(const float4*)(Kg + (size_t)(k0 + 64 + r)*DKH + c);
                rv[l] = *(const float4*)(Vg + (size_t)(k0 + 64 + r)*DKH + c);
            }
        }

        // mask
        int2 mk2[2][8];
#pragma unroll
        for (int rr = 0; rr < 2; rr++) {
            const int* mp = mask + (size_t)(b*SEQ + q0 + qw + g + rr*8)*SEQ + k0 + 2*t;
#pragma unroll
            for (int fn = 0; fn < 8; fn++) mk2[rr][fn] = *(const int2*)(mp + fn*8);
        }

        // S = Q K^T (Q pre-scaled by 1/8)
        float sc[8][4] = {};
#pragma unroll
        for (int ks = 0; ks < 8; ks++) {
            const int k = ks*8;
#pragma unroll
            for (int fn = 0; fn < 8; fn++) {
                unsigned bk[2];
                int c = fn*8 + g;
                bk[0] = Kb[c*FST + k + t];
                bk[1] = Kb[c*FST + k + t + 4];
                mma8(sc[fn], aq[ks], bk);
            }
        }

        // store prefetched half-tile, load+store second half (other buffer;
        // safe: last reads of that buffer finished before previous tile's sync)
        if (nxt) {
            unsigned* Kn = Ks + (buf^1)*64*FST;
            unsigned* Vn = Vs + (buf^1)*64*VST;
#pragma unroll
            for (int l = 0; l < 4; l++) {
                int lin = tid + l*128; int r = lin >> 4, c = (lin & 15)*4;
                *(uint4*)&Kn[r*FST + c] = cvt4(rk[l]);
                *(uint4*)&Vn[r*VST + c] = cvt4(rv[l]);
            }
#pragma unroll
            for (int l = 4; l < 8; l++) {
                int lin = tid + l*128; int r = lin >> 4, c = (lin & 15)*4;
                float4 k4 = *(const float4*)(Kg + (size_t)(k0 + 64 + r)*DKH + c);
                float4 v4 = *(const float4*)(Vg + (size_t)(k0 + 64 + r)*DKH + c);
                *(uint4*)&Kn[r*FST + c] = cvt4(k4);
                *(uint4*)&Vn[r*VST + c] = cvt4(v4);
            }
        }

        // mask + online softmax
#pragma unroll
        for (int rr = 0; rr < 2; rr++) {
#pragma unroll
            for (int fn = 0; fn < 8; fn++) {
                if (mk2[rr][fn].x == 0) sc[fn][rr*2]   = -1e30f;
                if (mk2[rr][fn].y == 0) sc[fn][rr*2+1] = -1e30f;
            }
            float rmax = -1e30f;
#pragma unroll
            for (int fn = 0; fn < 8; fn++)
                rmax = fmaxf(rmax, fmaxf(sc[fn][rr*2], sc[fn][rr*2+1]));
            rmax = fmaxf(rmax, __shfl_xor_sync(0xffffffffu, rmax, 1));
            rmax = fmaxf(rmax, __shfl_xor_sync(0xffffffffu, rmax, 2));
            float mn = fmaxf(m_[rr], rmax);
            float alpha = __expf(m_[rr] - mn);
            float rsum = 0.f;
#pragma unroll
            for (int fn = 0; fn < 8; fn++) {
                sc[fn][rr*2]   = __expf(sc[fn][rr*2]   - mn);
                sc[fn][rr*2+1] = __expf(sc[fn][rr*2+1] - mn);
                rsum += sc[fn][rr*2] + sc[fn][rr*2+1];
            }
            rsum += __shfl_xor_sync(0xffffffffu, rsum, 1);
            rsum += __shfl_xor_sync(0xffffffffu, rsum, 2);
            l_[rr] = l_[rr]*alpha + rsum;
            m_[rr] = mn;
#pragma unroll
            for (int fn = 0; fn < 8; fn++) { o[fn][rr*2] *= alpha; o[fn][rr*2+1] *= alpha; }
        }

        // write P (warp-private rows of Ps)
#pragma unroll
        for (int rr = 0; rr < 2; rr++) {
            int r = qw + g + rr*8;
#pragma unroll
            for (int fn = 0; fn < 8; fn++) {
                uint2 u;
                u.x = cvt_tf32(sc[fn][rr*2]);
                u.y = cvt_tf32(sc[fn][rr*2+1]);
                *(uint2*)&Ps[r*FST + fn*8 + 2*t] = u;
            }
        }
        __syncwarp();

        // O += P @ V   (V frag reads conflict-free at stride 72: 8t+g banks)
#pragma unroll
        for (int ks = 0; ks < 8; ks++) {
            const int k = ks*8, r = qw + g;
            unsigned ap[4];
            ap[0] = Ps[r*FST + k + t];     ap[1] = Ps[(r+8)*FST + k + t];
            ap[2] = Ps[r*FST + k + t + 4]; ap[3] = Ps[(r+8)*FST + k + t + 4];
#pragma unroll
            for (int fn = 0; fn < 8; fn++) {
                unsigned bv[2];
                bv[0] = Vb[(k+t)*VST   + fn*8 + g];
                bv[1] = Vb[(k+t+4)*VST + fn*8 + g];
                mma8(o[fn], ap, bv);
            }
        }
        __syncthreads();   // next-tile buffers written & this tile's reads done
    }

    // normalize + write merged [B,S, h*64+d]
#pragma unroll
    for (int rr = 0; rr < 2; rr++) {
        float inv = 1.0f / l_[rr];
        int row = q0 + qw + g + rr*8;
        float* op = Out + (size_t)(b*SEQ + row)*DMODEL + h*DKH + 2*t;
#pragma unroll
        for (int fn = 0; fn < 8; fn++) {
            float2 v;
            v.x = o[fn][rr*2]   * inv;
            v.y = o[fn][rr*2+1] * inv;
            *(float2*)(op + fn*8) = v;
        }
    }
}

// ---------------------------------------------------------------------------
extern "C" void kernel_launch(void* const* d_in, const int* in_sizes, int n_in,
                              void* d_out, int out_size)
{
    const float* q  = (const float*)d_in[0];
    const float* k  = (const float*)d_in[1];
    const float* v  = (const float*)d_in[2];
    const int*   mk = (const int*)  d_in[3];
    const float* wq = (const float*)d_in[4];
    const float* wk = (const float*)d_in[5];
    const float* wv = (const float*)d_in[6];
    const float* wo = (const float*)d_in[7];
    const float* bo = (const float*)d_in[8];
    float* out = (float*)d_out;

    float *qp, *kp, *vp, *ao;
    cudaGetSymbolAddress((void**)&qp, g_qp);
    cudaGetSymbolAddress((void**)&kp, g_kp);
    cudaGetSymbolAddress((void**)&vp, g_vp);
    cudaGetSymbolAddress((void**)&ao, g_ao);

    const int flash_smem = (2*64*FST + 2*64*VST + 64*FST) * 4;   // 89088 B
    cudaFuncSetAttribute(flash_tf32, cudaFuncAttributeMaxDynamicSharedMemorySize, flash_smem);

    dim3 gg(DMODEL/128, MR/128);   // (8, 32)
    gemm_tf32<<<gg, 128>>>(q, wq, nullptr, qp, 0.125f, 1);   // 1/sqrt(64) folded
    gemm_tf32<<<gg, 128>>>(k, wk, nullptr, kp, 1.0f, 1);
    gemm_tf32<<<gg, 128>>>(v, wv, nullptr, vp, 1.0f, 1);
    flash_tf32<<<dim3(SEQ/64, HEADS, BATCH), 128, flash_smem>>>(qp, kp, vp, mk, ao);
    gemm_tf32<<<gg, 128>>>(ao, wo, bo, out, 1.0f, 0);
}

// round 6
// speedup vs baseline: 9.8067x; 1.7731x over previous
#include <cuda_runtime.h>
#include <cuda_fp16.h>

#define DMODEL 1024
#define HEADS  16
#define DKH    64
#define BATCH  2
#define SEQ    2048
#define MR     (BATCH*SEQ)   // 4096 rows

// --------------------------- device scratch (no allocs) ---------------------
__device__ __half g_qh[MR*DMODEL];   // half copies of inputs
__device__ __half g_kh[MR*DMODEL];
__device__ __half g_vh[MR*DMODEL];
__device__ __half g_wqh[DMODEL*DMODEL];
__device__ __half g_wkh[DMODEL*DMODEL];
__device__ __half g_wvh[DMODEL*DMODEL];
__device__ __half g_woh[DMODEL*DMODEL];
__device__ __half g_qp[MR*DMODEL];   // projected, head-split [B,H,S,DKH], q pre-scaled
__device__ __half g_kp[MR*DMODEL];
__device__ __half g_vp[MR*DMODEL];
__device__ __half g_ao[MR*DMODEL];   // attention out, merged [B,S,H*DKH]

// --------------------------- helpers ----------------------------------------
__device__ __forceinline__ unsigned smem_u32(const void* p) {
    return (unsigned)__cvta_generic_to_shared(p);
}
__device__ __forceinline__ void cpa16(unsigned dst, const void* src) {
    asm volatile("cp.async.cg.shared.global [%0], [%1], 16;" :: "r"(dst), "l"(src));
}
__device__ __forceinline__ void cpa_commit() { asm volatile("cp.async.commit_group;"); }
__device__ __forceinline__ void cpa_wait1()  { asm volatile("cp.async.wait_group 1;"); }

// D(16x8) += A(16x16) * B(16x8), f16 in, f32 accum
__device__ __forceinline__ void mma16(float* c, const unsigned* a, const unsigned* b) {
    asm volatile("mma.sync.aligned.m16n8k16.row.col.f32.f16.f16.f32 "
        "{%0,%1,%2,%3}, {%4,%5,%6,%7}, {%8,%9}, {%0,%1,%2,%3};"
        : "+f"(c[0]), "+f"(c[1]), "+f"(c[2]), "+f"(c[3])
        : "r"(a[0]), "r"(a[1]), "r"(a[2]), "r"(a[3]), "r"(b[0]), "r"(b[1]));
}
__device__ __forceinline__ void ldmx4t(unsigned& r0, unsigned& r1, unsigned& r2, unsigned& r3, unsigned a) {
    asm volatile("ldmatrix.sync.aligned.m8n8.x4.trans.shared.b16 {%0,%1,%2,%3}, [%4];"
        : "=r"(r0), "=r"(r1), "=r"(r2), "=r"(r3) : "r"(a));
}

// --------------------------- fp32 -> fp16 converter --------------------------
__global__ void f2h4(const float* __restrict__ s0, const float* __restrict__ s1,
                     const float* __restrict__ s2, const float* __restrict__ s3,
                     __half* d0, __half* d1, __half* d2, __half* d3, int n4)
{
    const float* s; __half* d;
    switch (blockIdx.y) {
        case 0: s = s0; d = d0; break;
        case 1: s = s1; d = d1; break;
        case 2: s = s2; d = d2; break;
        default: s = s3; d = d3; break;
    }
    for (int i = blockIdx.x*blockDim.x + threadIdx.x; i < n4; i += gridDim.x*blockDim.x) {
        float4 v = ((const float4*)s)[i];
        half2 h0 = __floats2half2_rn(v.x, v.y);
        half2 h1 = __floats2half2_rn(v.z, v.w);
        ((half2*)d)[2*i]   = h0;
        ((half2*)d)[2*i+1] = h1;
    }
}

// ---------------------------------------------------------------------------
// C = scale * A @ W^T (+bias). A[M,1024] half K-major, W[N,1024] half K-major.
// CTA 128x128, 4 warps (2x2), warp tile 64x64, Kt=32, 3-stage cp.async pipe.
// split=1: C half, head-split [B,H,S,DKH]; split=0: C float, +bias.
// ---------------------------------------------------------------------------
#define GLD 40   // smem row stride in halves (80B, 16B-aligned, conflict-free)
__global__ __launch_bounds__(128, 2) void gemm_h(
    const __half* __restrict__ A, const __half* __restrict__ W,
    const float* __restrict__ bias, void* __restrict__ Cv,
    float scale, int split)
{
    extern __shared__ __half sm[];
    __half* smA = sm;                 // 3 x [128][GLD]
    __half* smB = sm + 3*128*GLD;     // 3 x [128][GLD]

    const int tid = threadIdx.x, lane = tid & 31;
    const int g = lane >> 2, t = lane & 3, wid = tid >> 5;
    const int wm = (wid & 1) * 64, wn = (wid >> 1) * 64;
    const int m0 = blockIdx.y * 128, n0 = blockIdx.x * 128;

    // 128 rows x 4 chunks(16B) per matrix per tile; 4 chunks/thread
    int crow[4], coff[4];
#pragma unroll
    for (int l = 0; l < 4; l++) {
        int c = tid + l*128;
        crow[l] = c >> 2; coff[l] = (c & 3) * 8;
    }
    const __half* Ag = A + (size_t)m0 * DMODEL;
    const __half* Wg = W + (size_t)n0 * DMODEL;

    auto issue = [&](int tile) {
        int buf = tile % 3, k0 = tile * 32;
        unsigned da = smem_u32(smA + buf*128*GLD);
        unsigned db = smem_u32(smB + buf*128*GLD);
#pragma unroll
        for (int l = 0; l < 4; l++) {
            cpa16(da + (crow[l]*GLD + coff[l])*2, Ag + (size_t)crow[l]*DMODEL + k0 + coff[l]);
            cpa16(db + (crow[l]*GLD + coff[l])*2, Wg + (size_t)crow[l]*DMODEL + k0 + coff[l]);
        }
    };
    issue(0); cpa_commit();
    issue(1); cpa_commit();

    float acc[4][8][4] = {};

    for (int i = 0; i < 32; i++) {
        cpa_wait1();
        __syncthreads();
        if (i + 2 < 32) issue(i + 2);
        cpa_commit();

        const __half* As = smA + (i % 3)*128*GLD;
        const __half* Bs = smB + (i % 3)*128*GLD;
#pragma unroll
        for (int ks = 0; ks < 2; ks++) {
            const int k = ks * 16;
            unsigned af[4][4], bf[8][2];
#pragma unroll
            for (int fm = 0; fm < 4; fm++) {
                int r = wm + fm*16 + g;
                af[fm][0] = *(const unsigned*)&As[r*GLD + k + 2*t];
                af[fm][1] = *(const unsigned*)&As[(r+8)*GLD + k + 2*t];
                af[fm][2] = *(const unsigned*)&As[r*GLD + k + 8 + 2*t];
                af[fm][3] = *(const unsigned*)&As[(r+8)*GLD + k + 8 + 2*t];
            }
#pragma unroll
            for (int fn = 0; fn < 8; fn++) {
                int c = wn + fn*8 + g;
                bf[fn][0] = *(const unsigned*)&Bs[c*GLD + k + 2*t];
                bf[fn][1] = *(const unsigned*)&Bs[c*GLD + k + 8 + 2*t];
            }
#pragma unroll
            for (int fm = 0; fm < 4; fm++)
#pragma unroll
                for (int fn = 0; fn < 8; fn++) mma16(acc[fm][fn], af[fm], bf[fn]);
        }
        __syncthreads();
    }

#pragma unroll
    for (int fn = 0; fn < 8; fn++) {
        int n = n0 + wn + fn*8 + 2*t;
        float b0 = 0.f, b1 = 0.f;
        if (bias) { b0 = bias[n]; b1 = bias[n+1]; }
#pragma unroll
        for (int fm = 0; fm < 4; fm++) {
#pragma unroll
            for (int rr = 0; rr < 2; rr++) {
                int m = m0 + wm + fm*16 + g + rr*8;
                float vx = acc[fm][fn][rr*2]   * scale + b0;
                float vy = acc[fm][fn][rr*2+1] * scale + b1;
                if (split) {
                    int bb = m >> 11, ss = m & (SEQ-1);
                    int hh = n >> 6,  dd = n & 63;
                    __half* C = (__half*)Cv;
                    *(half2*)(C + (size_t)(((bb*HEADS + hh)*SEQ) + ss)*DKH + dd) =
                        __floats2half2_rn(vx, vy);
                } else {
                    float* C = (float*)Cv;
                    *(float2*)(C + (size_t)m*DMODEL + n) = make_float2(vx, vy);
                }
            }
        }
    }
}

// ---------------------------------------------------------------------------
// Flash attention fp16. Br=64 (4 warps x 16 rows), Bc=64, 3-stage cp.async
// K/V pipeline, Q-frags register-resident, V transposed via ldmatrix.x4.trans.
// ---------------------------------------------------------------------------
#define FLD 72   // smem row stride in halves (144B)
#define FTS (64*FLD)
__global__ __launch_bounds__(128, 3) void flash_h(
    const __half* __restrict__ Qp, const __half* __restrict__ Kp,
    const __half* __restrict__ Vp, const int* __restrict__ mask,
    __half* __restrict__ Out)
{
    extern __shared__ __half fsm[];
    __half* Qs = fsm;             // [64][FLD]
    __half* Ks = fsm + FTS;       // 3 x [64][FLD]
    __half* Vs = fsm + 4*FTS;     // 3 x [64][FLD]
    __half* Ps = fsm + 7*FTS;     // [64][FLD]

    const int tid = threadIdx.x, lane = tid & 31;
    const int g = lane >> 2, t = lane & 3, wid = tid >> 5;
    const int q0 = blockIdx.x * 64, h = blockIdx.y, b = blockIdx.z;
    const int qw = wid * 16;

    const __half* Qg = Qp + (size_t)((b*HEADS + h)*SEQ + q0)*DKH;
    const __half* Kg = Kp + (size_t)((b*HEADS + h)*SEQ)*DKH;
    const __half* Vg = Vp + (size_t)((b*HEADS + h)*SEQ)*DKH;

    // 64 rows x 8 chunks(16B) = 512 chunks per tile; 4/thread
    int crow[4], coff[4];
#pragma unroll
    for (int l = 0; l < 4; l++) {
        int c = tid + l*128;
        crow[l] = c >> 3; coff[l] = (c & 7) * 8;
    }

    auto issue_kv = [&](int tile) {
        int buf = tile % 3, k0 = tile * 64;
        unsigned dk = smem_u32(Ks + buf*FTS);
        unsigned dv = smem_u32(Vs + buf*FTS);
#pragma unroll
        for (int l = 0; l < 4; l++) {
            cpa16(dk + (crow[l]*FLD + coff[l])*2, Kg + (size_t)(k0 + crow[l])*DKH + coff[l]);
            cpa16(dv + (crow[l]*FLD + coff[l])*2, Vg + (size_t)(k0 + crow[l])*DKH + coff[l]);
        }
    };
    {   // group 0: Q + tile 0
        unsigned dq = smem_u32(Qs);
#pragma unroll
        for (int l = 0; l < 4; l++)
            cpa16(dq + (crow[l]*FLD + coff[l])*2, Qg + (size_t)crow[l]*DKH + coff[l]);
        issue_kv(0); cpa_commit();
        issue_kv(1); cpa_commit();
    }

    // per-thread constant parts of ldmatrix addresses
    const int vrow_c = (lane & 7) + ((lane >> 3) & 1) * 8;   // row within 16-k block
    const int vcol_c = (lane >> 4) * 8;                       // 0 or 8 within fn-pair

    unsigned aq[4][4];
    float o[8][4] = {};
    float m_[2] = {-1e30f, -1e30f};
    float l_[2] = {0.f, 0.f};

    for (int i = 0; i < 32; i++) {
        const int k0 = i * 64;
        cpa_wait1();
        __syncthreads();
        if (i + 2 < 32) issue_kv(i + 2);
        cpa_commit();

        if (i == 0) {   // Q frags -> registers (once)
#pragma unroll
            for (int ks = 0; ks < 4; ks++) {
                const int r = qw + g, k = ks*16;
                aq[ks][0] = *(const unsigned*)&Qs[r*FLD + k + 2*t];
                aq[ks][1] = *(const unsigned*)&Qs[(r+8)*FLD + k + 2*t];
                aq[ks][2] = *(const unsigned*)&Qs[r*FLD + k + 8 + 2*t];
                aq[ks][3] = *(const unsigned*)&Qs[(r+8)*FLD + k + 8 + 2*t];
            }
        }

        // mask loads (hidden under S-MMA)
        int2 mk2[2][8];
#pragma unroll
        for (int rr = 0; rr < 2; rr++) {
            const int* mp = mask + (size_t)(b*SEQ + q0 + qw + g + rr*8)*SEQ + k0 + 2*t;
#pragma unroll
            for (int fn = 0; fn < 8; fn++) mk2[rr][fn] = *(const int2*)(mp + fn*8);
        }

        const __half* Kb = Ks + (i % 3)*FTS;
        const __half* Vb = Vs + (i % 3)*FTS;

        // S = Q K^T (Q pre-scaled by 1/8)
        float sc[8][4] = {};
#pragma unroll
        for (int ks = 0; ks < 4; ks++) {
            const int k = ks*16;
#pragma unroll
            for (int fn = 0; fn < 8; fn++) {
                unsigned bk[2];
                const int c = fn*8 + g;
                bk[0] = *(const unsigned*)&Kb[c*FLD + k + 2*t];
                bk[1] = *(const unsigned*)&Kb[c*FLD + k + 8 + 2*t];
                mma16(sc[fn], aq[ks], bk);
            }
        }

        // mask + online softmax
#pragma unroll
        for (int rr = 0; rr < 2; rr++) {
#pragma unroll
            for (int fn = 0; fn < 8; fn++) {
                if (mk2[rr][fn].x == 0) sc[fn][rr*2]   = -1e30f;
                if (mk2[rr][fn].y == 0) sc[fn][rr*2+1] = -1e30f;
            }
            float rmax = -1e30f;
#pragma unroll
            for (int fn = 0; fn < 8; fn++)
                rmax = fmaxf(rmax, fmaxf(sc[fn][rr*2], sc[fn][rr*2+1]));
            rmax = fmaxf(rmax, __shfl_xor_sync(0xffffffffu, rmax, 1));
            rmax = fmaxf(rmax, __shfl_xor_sync(0xffffffffu, rmax, 2));
            float mn = fmaxf(m_[rr], rmax);
            float alpha = __expf(m_[rr] - mn);
            float rsum = 0.f;
#pragma unroll
            for (int fn = 0; fn < 8; fn++) {
                sc[fn][rr*2]   = __expf(sc[fn][rr*2]   - mn);
                sc[fn][rr*2+1] = __expf(sc[fn][rr*2+1] - mn);
                rsum += sc[fn][rr*2] + sc[fn][rr*2+1];
            }
            rsum += __shfl_xor_sync(0xffffffffu, rsum, 1);
            rsum += __shfl_xor_sync(0xffffffffu, rsum, 2);
            l_[rr] = l_[rr]*alpha + rsum;
            m_[rr] = mn;
#pragma unroll
            for (int fn = 0; fn < 8; fn++) { o[fn][rr*2] *= alpha; o[fn][rr*2+1] *= alpha; }
        }

        // P (fp16) into warp-private rows of Ps
#pragma unroll
        for (int rr = 0; rr < 2; rr++) {
            const int r = qw + g + rr*8;
#pragma unroll
            for (int fn = 0; fn < 8; fn++)
                *(half2*)&Ps[r*FLD + fn*8 + 2*t] =
                    __floats2half2_rn(sc[fn][rr*2], sc[fn][rr*2+1]);
        }
        __syncwarp();

        // O += P @ V  (V transposed on the fly via ldmatrix.x4.trans)
        const unsigned vbase = smem_u32(Vb);
#pragma unroll
        for (int ks = 0; ks < 4; ks++) {
            const int k = ks*16, r = qw + g;
            unsigned ap[4];
            ap[0] = *(const unsigned*)&Ps[r*FLD + k + 2*t];
            ap[1] = *(const unsigned*)&Ps[(r+8)*FLD + k + 2*t];
            ap[2] = *(const unsigned*)&Ps[r*FLD + k + 8 + 2*t];
            ap[3] = *(const unsigned*)&Ps[(r+8)*FLD + k + 8 + 2*t];
#pragma unroll
            for (int fp = 0; fp < 4; fp++) {
                unsigned r0, r1, r2, r3;
                unsigned addr = vbase + ((k + vrow_c)*FLD + fp*16 + vcol_c)*2;
                ldmx4t(r0, r1, r2, r3, addr);
                unsigned b0[2] = {r0, r1}, b1[2] = {r2, r3};
                mma16(o[2*fp],   ap, b0);
                mma16(o[2*fp+1], ap, b1);
            }
        }
        __syncthreads();
    }

    // normalize + half store, merged [B,S, h*64+d]
#pragma unroll
    for (int rr = 0; rr < 2; rr++) {
        float inv = 1.0f / l_[rr];
        int row = q0 + qw + g + rr*8;
        __half* op = Out + (size_t)(b*SEQ + row)*DMODEL + h*DKH + 2*t;
#pragma unroll
        for (int fn = 0; fn < 8; fn++)
            *(half2*)(op + fn*8) = __floats2half2_rn(o[fn][rr*2]*inv, o[fn][rr*2+1]*inv);
    }
}

// ---------------------------------------------------------------------------
extern "C" void kernel_launch(void* const* d_in, const int* in_sizes, int n_in,
                              void* d_out, int out_size)
{
    const float* q  = (const float*)d_in[0];
    const float* k  = (const float*)d_in[1];
    const float* v  = (const float*)d_in[2];
    const int*   mk = (const int*)  d_in[3];
    const float* wq = (const float*)d_in[4];
    const float* wk = (const float*)d_in[5];
    const float* wv = (const float*)d_in[6];
    const float* wo = (const float*)d_in[7];
    const float* bo = (const float*)d_in[8];
    float* out = (float*)d_out;

    __half *qh, *kh, *vh, *wqh, *wkh, *wvh, *woh, *qp, *kp, *vp, *ao;
    cudaGetSymbolAddress((void**)&qh,  g_qh);
    cudaGetSymbolAddress((void**)&kh,  g_kh);
    cudaGetSymbolAddress((void**)&vh,  g_vh);
    cudaGetSymbolAddress((void**)&wqh, g_wqh);
    cudaGetSymbolAddress((void**)&wkh, g_wkh);
    cudaGetSymbolAddress((void**)&wvh, g_wvh);
    cudaGetSymbolAddress((void**)&woh, g_woh);
    cudaGetSymbolAddress((void**)&qp,  g_qp);
    cudaGetSymbolAddress((void**)&kp,  g_kp);
    cudaGetSymbolAddress((void**)&vp,  g_vp);
    cudaGetSymbolAddress((void**)&ao,  g_ao);

    const int gemm_smem  = 6 * 128 * GLD * 2;      // 61440 B
    const int flash_smem = 8 * FTS * 2;            // 73728 B
    cudaFuncSetAttribute(gemm_h,  cudaFuncAttributeMaxDynamicSharedMemorySize, gemm_smem);
    cudaFuncSetAttribute(flash_h, cudaFuncAttributeMaxDynamicSharedMemorySize, flash_smem);

    // fp32 -> fp16 conversions
    f2h4<<<dim3(512, 3), 256>>>(q, k, v, nullptr, qh, kh, vh, nullptr, MR*DMODEL/4);
    f2h4<<<dim3(128, 4), 256>>>(wq, wk, wv, wo, wqh, wkh, wvh, woh, DMODEL*DMODEL/4);

    dim3 gg(DMODEL/128, MR/128);   // (8, 32)
    gemm_h<<<gg, 128, gemm_smem>>>(qh, wqh, nullptr, qp, 0.125f, 1);  // 1/sqrt(64) folded
    gemm_h<<<gg, 128, gemm_smem>>>(kh, wkh, nullptr, kp, 1.0f, 1);
    gemm_h<<<gg, 128, gemm_smem>>>(vh, wvh, nullptr, vp, 1.0f, 1);
    flash_h<<<dim3(SEQ/64, HEADS, BATCH), 128, flash_smem>>>(qp, kp, vp, mk, ao);
    gemm_h<<<gg, 128, gemm_smem>>>(ao, woh, bo, out, 1.0f, 0);
}

// round 7
// speedup vs baseline: 9.9698x; 1.0166x over previous
#include <cuda_runtime.h>
#include <cuda_fp16.h>

#define DMODEL 1024
#define HEADS  16
#define DKH    64
#define BATCH  2
#define SEQ    2048
#define MR     (BATCH*SEQ)   // 4096 rows

// --------------------------- device scratch (no allocs) ---------------------
__device__ __half g_qh[MR*DMODEL];   // half copies of inputs
__device__ __half g_kh[MR*DMODEL];
__device__ __half g_vh[MR*DMODEL];
__device__ __half g_wqh[DMODEL*DMODEL];
__device__ __half g_wkh[DMODEL*DMODEL];
__device__ __half g_wvh[DMODEL*DMODEL];
__device__ __half g_woh[DMODEL*DMODEL];
__device__ __half g_qp[MR*DMODEL];   // projected, head-split [B,H,S,DKH], q pre-scaled
__device__ __half g_kp[MR*DMODEL];
__device__ __half g_vp[MR*DMODEL];
__device__ __half g_ao[MR*DMODEL];   // attention out, merged [B,S,H*DKH]

// --------------------------- helpers ----------------------------------------
__device__ __forceinline__ unsigned smem_u32(const void* p) {
    return (unsigned)__cvta_generic_to_shared(p);
}
__device__ __forceinline__ void cpa16(unsigned dst, const void* src) {
    asm volatile("cp.async.cg.shared.global [%0], [%1], 16;" :: "r"(dst), "l"(src));
}
__device__ __forceinline__ void cpa_commit() { asm volatile("cp.async.commit_group;"); }
__device__ __forceinline__ void cpa_wait1()  { asm volatile("cp.async.wait_group 1;"); }

// D(16x8) += A(16x16) * B(16x8), f16 in, f32 accum
__device__ __forceinline__ void mma16(float* c, const unsigned* a, const unsigned* b) {
    asm volatile("mma.sync.aligned.m16n8k16.row.col.f32.f16.f16.f32 "
        "{%0,%1,%2,%3}, {%4,%5,%6,%7}, {%8,%9}, {%0,%1,%2,%3};"
        : "+f"(c[0]), "+f"(c[1]), "+f"(c[2]), "+f"(c[3])
        : "r"(a[0]), "r"(a[1]), "r"(a[2]), "r"(a[3]), "r"(b[0]), "r"(b[1]));
}
__device__ __forceinline__ void ldmx4(unsigned& r0, unsigned& r1, unsigned& r2, unsigned& r3, unsigned a) {
    asm volatile("ldmatrix.sync.aligned.m8n8.x4.shared.b16 {%0,%1,%2,%3}, [%4];"
        : "=r"(r0), "=r"(r1), "=r"(r2), "=r"(r3) : "r"(a));
}
__device__ __forceinline__ void ldmx4t(unsigned& r0, unsigned& r1, unsigned& r2, unsigned& r3, unsigned a) {
    asm volatile("ldmatrix.sync.aligned.m8n8.x4.trans.shared.b16 {%0,%1,%2,%3}, [%4];"
        : "=r"(r0), "=r"(r1), "=r"(r2), "=r"(r3) : "r"(a));
}
__device__ __forceinline__ unsigned packh2(float a, float b) {
    half2 h = __floats2half2_rn(a, b);
    return *reinterpret_cast<unsigned*>(&h);
}

// --------------------------- fp32 -> fp16 converter --------------------------
__global__ void f2h4(const float* __restrict__ s0, const float* __restrict__ s1,
                     const float* __restrict__ s2, const float* __restrict__ s3,
                     __half* d0, __half* d1, __half* d2, __half* d3, int n4)
{
    const float* s; __half* d;
    switch (blockIdx.y) {
        case 0: s = s0; d = d0; break;
        case 1: s = s1; d = d1; break;
        case 2: s = s2; d = d2; break;
        default: s = s3; d = d3; break;
    }
    for (int i = blockIdx.x*blockDim.x + threadIdx.x; i < n4; i += gridDim.x*blockDim.x) {
        float4 v = ((const float4*)s)[i];
        ((half2*)d)[2*i]   = __floats2half2_rn(v.x, v.y);
        ((half2*)d)[2*i+1] = __floats2half2_rn(v.z, v.w);
    }
}

// ---------------------------------------------------------------------------
// C = scale * A @ W^T (+bias). z = blockIdx.z selects (A, W, C, scale).
// CTA 128x128, 256 threads / 8 warps (2m x 4n), warp tile 64x32, Kt=32,
// 3-stage cp.async pipeline.
// split=1: C half, head-split [B,H,S,DKH]; split=0: C float, +bias.
// ---------------------------------------------------------------------------
struct GemmArgs {
    const __half* A[3]; const __half* W[3]; void* C[3];
    float scale[3]; const float* bias; int split;
};

#define GLD 40   // smem row stride in halves (80B, conflict-free)
__global__ __launch_bounds__(256, 2) void gemm_h(GemmArgs ga)
{
    extern __shared__ __half sm[];
    __half* smA = sm;                 // 3 x [128][GLD]
    __half* smB = sm + 3*128*GLD;     // 3 x [128][GLD]

    const int tid = threadIdx.x, lane = tid & 31;
    const int g = lane >> 2, t = lane & 3, wid = tid >> 5;
    const int wm = (wid & 1) * 64, wn = (wid >> 1) * 32;
    const int m0 = blockIdx.y * 128, n0 = blockIdx.x * 128;
    const int z = blockIdx.z;

    const __half* Ag = ga.A[z] + (size_t)m0 * DMODEL;
    const __half* Wg = ga.W[z] + (size_t)n0 * DMODEL;
    const float scale = ga.scale[z];

    // 128 rows x 4 chunks(16B) per matrix per tile; 2 chunks/thread
    int crow[2], coff[2];
#pragma unroll
    for (int l = 0; l < 2; l++) {
        int c = tid + l*256;
        crow[l] = c >> 2; coff[l] = (c & 3) * 8;
    }

    auto issue = [&](int tile) {
        int buf = tile % 3, k0 = tile * 32;
        unsigned da = smem_u32(smA + buf*128*GLD);
        unsigned db = smem_u32(smB + buf*128*GLD);
#pragma unroll
        for (int l = 0; l < 2; l++) {
            cpa16(da + (crow[l]*GLD + coff[l])*2, Ag + (size_t)crow[l]*DMODEL + k0 + coff[l]);
            cpa16(db + (crow[l]*GLD + coff[l])*2, Wg + (size_t)crow[l]*DMODEL + k0 + coff[l]);
        }
    };
    issue(0); cpa_commit();
    issue(1); cpa_commit();

    float acc[4][4][4] = {};

    for (int i = 0; i < 32; i++) {
        cpa_wait1();
        __syncthreads();
        if (i + 2 < 32) issue(i + 2);
        cpa_commit();

        const __half* As = smA + (i % 3)*128*GLD;
        const __half* Bs = smB + (i % 3)*128*GLD;
#pragma unroll
        for (int ks = 0; ks < 2; ks++) {
            const int k = ks * 16;
            unsigned af[4][4], bf[4][2];
#pragma unroll
            for (int fm = 0; fm < 4; fm++) {
                int r = wm + fm*16 + g;
                af[fm][0] = *(const unsigned*)&As[r*GLD + k + 2*t];
                af[fm][1] = *(const unsigned*)&As[(r+8)*GLD + k + 2*t];
                af[fm][2] = *(const unsigned*)&As[r*GLD + k + 8 + 2*t];
                af[fm][3] = *(const unsigned*)&As[(r+8)*GLD + k + 8 + 2*t];
            }
#pragma unroll
            for (int fn = 0; fn < 4; fn++) {
                int c = wn + fn*8 + g;
                bf[fn][0] = *(const unsigned*)&Bs[c*GLD + k + 2*t];
                bf[fn][1] = *(const unsigned*)&Bs[c*GLD + k + 8 + 2*t];
            }
#pragma unroll
            for (int fm = 0; fm < 4; fm++)
#pragma unroll
                for (int fn = 0; fn < 4; fn++) mma16(acc[fm][fn], af[fm], bf[fn]);
        }
        __syncthreads();
    }

#pragma unroll
    for (int fn = 0; fn < 4; fn++) {
        int n = n0 + wn + fn*8 + 2*t;
        float b0 = 0.f, b1 = 0.f;
        if (ga.bias) { b0 = ga.bias[n]; b1 = ga.bias[n+1]; }
#pragma unroll
        for (int fm = 0; fm < 4; fm++) {
#pragma unroll
            for (int rr = 0; rr < 2; rr++) {
                int m = m0 + wm + fm*16 + g + rr*8;
                float vx = acc[fm][fn][rr*2]   * scale + b0;
                float vy = acc[fm][fn][rr*2+1] * scale + b1;
                if (ga.split) {
                    int bb = m >> 11, ss = m & (SEQ-1);
                    int hh = n >> 6,  dd = n & 63;
                    __half* C = (__half*)ga.C[z];
                    *(half2*)(C + (size_t)(((bb*HEADS + hh)*SEQ) + ss)*DKH + dd) =
                        __floats2half2_rn(vx, vy);
                } else {
                    float* C = (float*)ga.C[z];
                    *(float2*)(C + (size_t)m*DMODEL + n) = make_float2(vx, vy);
                }
            }
        }
    }
}

// ---------------------------------------------------------------------------
// Flash attention fp16. Br=64 (4 warps x 16 rows), Bc=64, 3-stage cp.async
// K/V pipeline. Q-frags register-resident; K-frags via ldmatrix.x4;
// P stays in registers (S C-frag == PV A-frag layout); V transposed via
// ldmatrix.x4.trans. One __syncthreads per tile.
// ---------------------------------------------------------------------------
#define FLD 72   // smem row stride in halves (144B)
#define FTS (64*FLD)
__global__ __launch_bounds__(128, 3) void flash_h(
    const __half* __restrict__ Qp, const __half* __restrict__ Kp,
    const __half* __restrict__ Vp, const int* __restrict__ mask,
    __half* __restrict__ Out)
{
    extern __shared__ __half fsm[];
    __half* Qs = fsm;             // [64][FLD]
    __half* Ks = fsm + FTS;       // 3 x [64][FLD]
    __half* Vs = fsm + 4*FTS;     // 3 x [64][FLD]

    const int tid = threadIdx.x, lane = tid & 31;
    const int g = lane >> 2, t = lane & 3, wid = tid >> 5;
    const int q0 = blockIdx.x * 64, h = blockIdx.y, b = blockIdx.z;
    const int qw = wid * 16;

    const __half* Qg = Qp + (size_t)((b*HEADS + h)*SEQ + q0)*DKH;
    const __half* Kg = Kp + (size_t)((b*HEADS + h)*SEQ)*DKH;
    const __half* Vg = Vp + (size_t)((b*HEADS + h)*SEQ)*DKH;

    // 64 rows x 8 chunks(16B) = 512 chunks per tile; 4/thread
    int crow[4], coff[4];
#pragma unroll
    for (int l = 0; l < 4; l++) {
        int c = tid + l*128;
        crow[l] = c >> 3; coff[l] = (c & 7) * 8;
    }

    auto issue_kv = [&](int tile) {
        int buf = tile % 3, k0 = tile * 64;
        unsigned dk = smem_u32(Ks + buf*FTS);
        unsigned dv = smem_u32(Vs + buf*FTS);
#pragma unroll
        for (int l = 0; l < 4; l++) {
            cpa16(dk + (crow[l]*FLD + coff[l])*2, Kg + (size_t)(k0 + crow[l])*DKH + coff[l]);
            cpa16(dv + (crow[l]*FLD + coff[l])*2, Vg + (size_t)(k0 + crow[l])*DKH + coff[l]);
        }
    };
    {   // group 0: Q + tile 0
        unsigned dq = smem_u32(Qs);
#pragma unroll
        for (int l = 0; l < 4; l++)
            cpa16(dq + (crow[l]*FLD + coff[l])*2, Qg + (size_t)crow[l]*DKH + coff[l]);
        issue_kv(0); cpa_commit();
        issue_kv(1); cpa_commit();
    }

    // ldmatrix per-thread address constants
    const int krow_c = ((lane >> 4) & 1) * 8 + (lane & 7);  // row within fn-pair (K, non-trans)
    const int kkh    = ((lane >> 3) & 1) * 8;               // k-half select (K)
    const int vrow_c = (lane & 7) + ((lane >> 3) & 1) * 8;  // row within 16-k block (V, trans)
    const int vcol_c = (lane >> 4) * 8;                     // col within fn-pair (V)

    unsigned aq[4][4];
    float o[8][4] = {};
    float m_[2] = {-1e30f, -1e30f};
    float l_[2] = {0.f, 0.f};

    for (int i = 0; i < 32; i++) {
        const int k0 = i * 64;
        cpa_wait1();
        __syncthreads();
        if (i + 2 < 32) issue_kv(i + 2);
        cpa_commit();

        if (i == 0) {   // Q frags -> registers (once)
#pragma unroll
            for (int ks = 0; ks < 4; ks++) {
                const int r = qw + g, k = ks*16;
                aq[ks][0] = *(const unsigned*)&Qs[r*FLD + k + 2*t];
                aq[ks][1] = *(const unsigned*)&Qs[(r+8)*FLD + k + 2*t];
                aq[ks][2] = *(const unsigned*)&Qs[r*FLD + k + 8 + 2*t];
                aq[ks][3] = *(const unsigned*)&Qs[(r+8)*FLD + k + 8 + 2*t];
            }
        }

        // mask loads (hidden under S-MMA)
        int2 mk2[2][8];
#pragma unroll
        for (int rr = 0; rr < 2; rr++) {
            const int* mp = mask + (size_t)(b*SEQ + q0 + qw + g + rr*8)*SEQ + k0 + 2*t;
#pragma unroll
            for (int fn = 0; fn < 8; fn++) mk2[rr][fn] = *(const int2*)(mp + fn*8);
        }

        const __half* Kb = Ks + (i % 3)*FTS;
        const __half* Vb = Vs + (i % 3)*FTS;
        const unsigned kbase = smem_u32(Kb);
        const unsigned vbase = smem_u32(Vb);

        // S = Q K^T (Q pre-scaled by 1/8); K frags via ldmatrix.x4
        float sc[8][4] = {};
#pragma unroll
        for (int ks = 0; ks < 4; ks++) {
            const int k = ks*16;
#pragma unroll
            for (int p = 0; p < 4; p++) {
                unsigned r0, r1, r2, r3;
                unsigned addr = kbase + ((p*16 + krow_c)*FLD + k + kkh)*2;
                ldmx4(r0, r1, r2, r3, addr);
                unsigned b0[2] = {r0, r1}, b1[2] = {r2, r3};
                mma16(sc[2*p],   aq[ks], b0);
                mma16(sc[2*p+1], aq[ks], b1);
            }
        }

        // mask + online softmax
#pragma unroll
        for (int rr = 0; rr < 2; rr++) {
#pragma unroll
            for (int fn = 0; fn < 8; fn++) {
                if (mk2[rr][fn].x == 0) sc[fn][rr*2]   = -1e30f;
                if (mk2[rr][fn].y == 0) sc[fn][rr*2+1] = -1e30f;
            }
            float rmax = -1e30f;
#pragma unroll
            for (int fn = 0; fn < 8; fn++)
                rmax = fmaxf(rmax, fmaxf(sc[fn][rr*2], sc[fn][rr*2+1]));
            rmax = fmaxf(rmax, __shfl_xor_sync(0xffffffffu, rmax, 1));
            rmax = fmaxf(rmax, __shfl_xor_sync(0xffffffffu, rmax, 2));
            float mn = fmaxf(m_[rr], rmax);
            float alpha = __expf(m_[rr] - mn);
            float rsum = 0.f;
#pragma unroll
            for (int fn = 0; fn < 8; fn++) {
                sc[fn][rr*2]   = __expf(sc[fn][rr*2]   - mn);
                sc[fn][rr*2+1] = __expf(sc[fn][rr*2+1] - mn);
                rsum += sc[fn][rr*2] + sc[fn][rr*2+1];
            }
            rsum += __shfl_xor_sync(0xffffffffu, rsum, 1);
            rsum += __shfl_xor_sync(0xffffffffu, rsum, 2);
            l_[rr] = l_[rr]*alpha + rsum;
            m_[rr] = mn;
#pragma unroll
            for (int fn = 0; fn < 8; fn++) { o[fn][rr*2] *= alpha; o[fn][rr*2+1] *= alpha; }
        }

        // O += P @ V — P stays in registers: S C-frag layout == PV A-frag layout
#pragma unroll
        for (int ks = 0; ks < 4; ks++) {
            const int k = ks*16;
            unsigned ap[4];
            ap[0] = packh2(sc[2*ks][0],   sc[2*ks][1]);
            ap[1] = packh2(sc[2*ks][2],   sc[2*ks][3]);
            ap[2] = packh2(sc[2*ks+1][0], sc[2*ks+1][1]);
            ap[3] = packh2(sc[2*ks+1][2], sc[2*ks+1][3]);
#pragma unroll
            for (int fp = 0; fp < 4; fp++) {
                unsigned r0, r1, r2, r3;
                unsigned addr = vbase + ((k + vrow_c)*FLD + fp*16 + vcol_c)*2;
                ldmx4t(r0, r1, r2, r3, addr);
                unsigned b0[2] = {r0, r1}, b1[2] = {r2, r3};
                mma16(o[2*fp],   ap, b0);
                mma16(o[2*fp+1], ap, b1);
            }
        }
    }

    // normalize + half store, merged [B,S, h*64+d]
#pragma unroll
    for (int rr = 0; rr < 2; rr++) {
        float inv = 1.0f / l_[rr];
        int row = q0 + qw + g + rr*8;
        __half* op = Out + (size_t)(b*SEQ + row)*DMODEL + h*DKH + 2*t;
#pragma unroll
        for (int fn = 0; fn < 8; fn++)
            *(half2*)(op + fn*8) = __floats2half2_rn(o[fn][rr*2]*inv, o[fn][rr*2+1]*inv);
    }
}

// ---------------------------------------------------------------------------
extern "C" void kernel_launch(void* const* d_in, const int* in_sizes, int n_in,
                              void* d_out, int out_size)
{
    const float* q  = (const float*)d_in[0];
    const float* k  = (const float*)d_in[1];
    const float* v  = (const float*)d_in[2];
    const int*   mk = (const int*)  d_in[3];
    const float* wq = (const float*)d_in[4];
    const float* wk = (const float*)d_in[5];
    const float* wv = (const float*)d_in[6];
    const float* wo = (const float*)d_in[7];
    const float* bo = (const float*)d_in[8];
    float* out = (float*)d_out;

    __half *qh, *kh, *vh, *wqh, *wkh, *wvh, *woh, *qp, *kp, *vp, *ao;
    cudaGetSymbolAddress((void**)&qh,  g_qh);
    cudaGetSymbolAddress((void**)&kh,  g_kh);
    cudaGetSymbolAddress((void**)&vh,  g_vh);
    cudaGetSymbolAddress((void**)&wqh, g_wqh);
    cudaGetSymbolAddress((void**)&wkh, g_wkh);
    cudaGetSymbolAddress((void**)&wvh, g_wvh);
    cudaGetSymbolAddress((void**)&woh, g_woh);
    cudaGetSymbolAddress((void**)&qp,  g_qp);
    cudaGetSymbolAddress((void**)&kp,  g_kp);
    cudaGetSymbolAddress((void**)&vp,  g_vp);
    cudaGetSymbolAddress((void**)&ao,  g_ao);

    const int gemm_smem  = 6 * 128 * GLD * 2;      // 61440 B
    const int flash_smem = 7 * FTS * 2;            // 64512 B
    cudaFuncSetAttribute(gemm_h,  cudaFuncAttributeMaxDynamicSharedMemorySize, gemm_smem);
    cudaFuncSetAttribute(flash_h, cudaFuncAttributeMaxDynamicSharedMemorySize, flash_smem);

    // fp32 -> fp16 conversions
    f2h4<<<dim3(512, 3), 256>>>(q, k, v, nullptr, qh, kh, vh, nullptr, MR*DMODEL/4);
    f2h4<<<dim3(128, 4), 256>>>(wq, wk, wv, wo, wqh, wkh, wvh, woh, DMODEL*DMODEL/4);

    // fused QKV projections (z = 0,1,2); q pre-scaled by 1/sqrt(64)
    GemmArgs pa;
    pa.A[0] = qh;  pa.A[1] = kh;  pa.A[2] = vh;
    pa.W[0] = wqh; pa.W[1] = wkh; pa.W[2] = wvh;
    pa.C[0] = qp;  pa.C[1] = kp;  pa.C[2] = vp;
    pa.scale[0] = 0.125f; pa.scale[1] = 1.0f; pa.scale[2] = 1.0f;
    pa.bias = nullptr; pa.split = 1;
    gemm_h<<<dim3(DMODEL/128, MR/128, 3), 256, gemm_smem>>>(pa);

    flash_h<<<dim3(SEQ/64, HEADS, BATCH), 128, flash_smem>>>(qp, kp, vp, mk, ao);

    // output projection + bias
    GemmArgs oa;
    oa.A[0] = ao; oa.A[1] = nullptr; oa.A[2] = nullptr;
    oa.W[0] = woh; oa.W[1] = nullptr; oa.W[2] = nullptr;
    oa.C[0] = out; oa.C[1] = nullptr; oa.C[2] = nullptr;
    oa.scale[0] = 1.0f; oa.scale[1] = 1.0f; oa.scale[2] = 1.0f;
    oa.bias = bo; oa.split = 0;
    gemm_h<<<dim3(DMODEL/128, MR/128, 1), 256, gemm_smem>>>(oa);
}

// round 8
// speedup vs baseline: 10.6450x; 1.0677x over previous
#include <cuda_runtime.h>
#include <cuda_fp16.h>

#define DMODEL 1024
#define HEADS  16
#define DKH    64
#define BATCH  2
#define SEQ    2048
#define MR     (BATCH*SEQ)   // 4096 rows

// --------------------------- device scratch (no allocs) ---------------------
__device__ __half g_qh[MR*DMODEL];   // half copies of inputs
__device__ __half g_kh[MR*DMODEL];
__device__ __half g_vh[MR*DMODEL];
__device__ __half g_wqh[DMODEL*DMODEL];
__device__ __half g_wkh[DMODEL*DMODEL];
__device__ __half g_wvh[DMODEL*DMODEL];
__device__ __half g_woh[DMODEL*DMODEL];
__device__ __half g_qp[MR*DMODEL];   // projected, head-split [B,H,S,DKH], q scaled by log2e/8
__device__ __half g_kp[MR*DMODEL];
__device__ __half g_vp[MR*DMODEL];
__device__ __half g_ao[MR*DMODEL];   // attention out, merged [B,S,H*DKH]

// --------------------------- helpers ----------------------------------------
__device__ __forceinline__ unsigned smem_u32(const void* p) {
    return (unsigned)__cvta_generic_to_shared(p);
}
__device__ __forceinline__ void cpa16(unsigned dst, const void* src) {
    asm volatile("cp.async.cg.shared.global [%0], [%1], 16;" :: "r"(dst), "l"(src));
}
__device__ __forceinline__ void cpa_commit() { asm volatile("cp.async.commit_group;"); }
__device__ __forceinline__ void cpa_wait0()  { asm volatile("cp.async.wait_group 0;"); }
__device__ __forceinline__ void cpa_wait1()  { asm volatile("cp.async.wait_group 1;"); }

// D(16x8) += A(16x16) * B(16x8), f16 in, f32 accum
__device__ __forceinline__ void mma16(float* c, const unsigned* a, const unsigned* b) {
    asm volatile("mma.sync.aligned.m16n8k16.row.col.f32.f16.f16.f32 "
        "{%0,%1,%2,%3}, {%4,%5,%6,%7}, {%8,%9}, {%0,%1,%2,%3};"
        : "+f"(c[0]), "+f"(c[1]), "+f"(c[2]), "+f"(c[3])
        : "r"(a[0]), "r"(a[1]), "r"(a[2]), "r"(a[3]), "r"(b[0]), "r"(b[1]));
}
__device__ __forceinline__ void ldmx4(unsigned& r0, unsigned& r1, unsigned& r2, unsigned& r3, unsigned a) {
    asm volatile("ldmatrix.sync.aligned.m8n8.x4.shared.b16 {%0,%1,%2,%3}, [%4];"
        : "=r"(r0), "=r"(r1), "=r"(r2), "=r"(r3) : "r"(a));
}
__device__ __forceinline__ void ldmx4t(unsigned& r0, unsigned& r1, unsigned& r2, unsigned& r3, unsigned a) {
    asm volatile("ldmatrix.sync.aligned.m8n8.x4.trans.shared.b16 {%0,%1,%2,%3}, [%4];"
        : "=r"(r0), "=r"(r1), "=r"(r2), "=r"(r3) : "r"(a));
}
__device__ __forceinline__ unsigned packh2(float a, float b) {
    half2 h = __floats2half2_rn(a, b);
    return *reinterpret_cast<unsigned*>(&h);
}

// --------------------------- fp32 -> fp16 converter --------------------------
__global__ void f2h4(const float* __restrict__ s0, const float* __restrict__ s1,
                     const float* __restrict__ s2, const float* __restrict__ s3,
                     __half* d0, __half* d1, __half* d2, __half* d3, int n4)
{
    const float* s; __half* d;
    switch (blockIdx.y) {
        case 0: s = s0; d = d0; break;
        case 1: s = s1; d = d1; break;
        case 2: s = s2; d = d2; break;
        default: s = s3; d = d3; break;
    }
    for (int i = blockIdx.x*blockDim.x + threadIdx.x; i < n4; i += gridDim.x*blockDim.x) {
        float4 v = ((const float4*)s)[i];
        ((half2*)d)[2*i]   = __floats2half2_rn(v.x, v.y);
        ((half2*)d)[2*i+1] = __floats2half2_rn(v.z, v.w);
    }
}

// ---------------------------------------------------------------------------
// C = scale * A @ W^T (+bias). z = blockIdx.z selects (A, W, C, scale).
// CTA 128x128, 256 threads / 8 warps (2m x 4n), warp tile 64x32, Kt=32,
// 3-stage cp.async pipeline.
// split=1: C half, head-split [B,H,S,DKH]; split=0: C float, +bias.
// ---------------------------------------------------------------------------
struct GemmArgs {
    const __half* A[3]; const __half* W[3]; void* C[3];
    float scale[3]; const float* bias; int split;
};

#define GLD 40   // smem row stride in halves (80B, conflict-free)
__global__ __launch_bounds__(256, 2) void gemm_h(GemmArgs ga)
{
    extern __shared__ __half sm[];
    __half* smA = sm;                 // 3 x [128][GLD]
    __half* smB = sm + 3*128*GLD;     // 3 x [128][GLD]

    const int tid = threadIdx.x, lane = tid & 31;
    const int g = lane >> 2, t = lane & 3, wid = tid >> 5;
    const int wm = (wid & 1) * 64, wn = (wid >> 1) * 32;
    const int m0 = blockIdx.y * 128, n0 = blockIdx.x * 128;
    const int z = blockIdx.z;

    const __half* Ag = ga.A[z] + (size_t)m0 * DMODEL;
    const __half* Wg = ga.W[z] + (size_t)n0 * DMODEL;
    const float scale = ga.scale[z];

    int crow[2], coff[2];
#pragma unroll
    for (int l = 0; l < 2; l++) {
        int c = tid + l*256;
        crow[l] = c >> 2; coff[l] = (c & 3) * 8;
    }

    auto issue = [&](int tile) {
        int buf = tile % 3, k0 = tile * 32;
        unsigned da = smem_u32(smA + buf*128*GLD);
        unsigned db = smem_u32(smB + buf*128*GLD);
#pragma unroll
        for (int l = 0; l < 2; l++) {
            cpa16(da + (crow[l]*GLD + coff[l])*2, Ag + (size_t)crow[l]*DMODEL + k0 + coff[l]);
            cpa16(db + (crow[l]*GLD + coff[l])*2, Wg + (size_t)crow[l]*DMODEL + k0 + coff[l]);
        }
    };
    issue(0); cpa_commit();
    issue(1); cpa_commit();

    float acc[4][4][4] = {};

    for (int i = 0; i < 32; i++) {
        cpa_wait1();
        __syncthreads();
        if (i + 2 < 32) issue(i + 2);
        cpa_commit();

        const __half* As = smA + (i % 3)*128*GLD;
        const __half* Bs = smB + (i % 3)*128*GLD;
#pragma unroll
        for (int ks = 0; ks < 2; ks++) {
            const int k = ks * 16;
            unsigned af[4][4], bf[4][2];
#pragma unroll
            for (int fm = 0; fm < 4; fm++) {
                int r = wm + fm*16 + g;
                af[fm][0] = *(const unsigned*)&As[r*GLD + k + 2*t];
                af[fm][1] = *(const unsigned*)&As[(r+8)*GLD + k + 2*t];
                af[fm][2] = *(const unsigned*)&As[r*GLD + k + 8 + 2*t];
                af[fm][3] = *(const unsigned*)&As[(r+8)*GLD + k + 8 + 2*t];
            }
#pragma unroll
            for (int fn = 0; fn < 4; fn++) {
                int c = wn + fn*8 + g;
                bf[fn][0] = *(const unsigned*)&Bs[c*GLD + k + 2*t];
                bf[fn][1] = *(const unsigned*)&Bs[c*GLD + k + 8 + 2*t];
            }
#pragma unroll
            for (int fm = 0; fm < 4; fm++)
#pragma unroll
                for (int fn = 0; fn < 4; fn++) mma16(acc[fm][fn], af[fm], bf[fn]);
        }
        __syncthreads();
    }

#pragma unroll
    for (int fn = 0; fn < 4; fn++) {
        int n = n0 + wn + fn*8 + 2*t;
        float b0 = 0.f, b1 = 0.f;
        if (ga.bias) { b0 = ga.bias[n]; b1 = ga.bias[n+1]; }
#pragma unroll
        for (int fm = 0; fm < 4; fm++) {
#pragma unroll
            for (int rr = 0; rr < 2; rr++) {
                int m = m0 + wm + fm*16 + g + rr*8;
                float vx = acc[fm][fn][rr*2]   * scale + b0;
                float vy = acc[fm][fn][rr*2+1] * scale + b1;
                if (ga.split) {
                    int bb = m >> 11, ss = m & (SEQ-1);
                    int hh = n >> 6,  dd = n & 63;
                    __half* C = (__half*)ga.C[z];
                    *(half2*)(C + (size_t)(((bb*HEADS + hh)*SEQ) + ss)*DKH + dd) =
                        __floats2half2_rn(vx, vy);
                } else {
                    float* C = (float*)ga.C[z];
                    *(float2*)(C + (size_t)m*DMODEL + n) = make_float2(vx, vy);
                }
            }
        }
    }
}

// ---------------------------------------------------------------------------
// Flash attention fp16, exp2-domain softmax (log2e folded into Q scale).
// Br=64 (4 warps x 16 rows), Bc=64, 2-stage cp.async K/V pipeline (45KB smem
// -> 4 CTAs/SM). Q-frags register-resident; K via ldmatrix.x4; P in registers;
// V transposed via ldmatrix.x4.trans. One __syncthreads per tile.
// ---------------------------------------------------------------------------
#define FLD 72   // smem row stride in halves (144B)
#define FTS (64*FLD)
__global__ __launch_bounds__(128, 4) void flash_h(
    const __half* __restrict__ Qp, const __half* __restrict__ Kp,
    const __half* __restrict__ Vp, const int* __restrict__ mask,
    __half* __restrict__ Out)
{
    extern __shared__ __half fsm[];
    __half* Qs = fsm;             // [64][FLD]
    __half* Ks = fsm + FTS;       // 2 x [64][FLD]
    __half* Vs = fsm + 3*FTS;     // 2 x [64][FLD]

    const int tid = threadIdx.x, lane = tid & 31;
    const int g = lane >> 2, t = lane & 3, wid = tid >> 5;
    const int q0 = blockIdx.x * 64, h = blockIdx.y, b = blockIdx.z;
    const int qw = wid * 16;

    const __half* Qg = Qp + (size_t)((b*HEADS + h)*SEQ + q0)*DKH;
    const __half* Kg = Kp + (size_t)((b*HEADS + h)*SEQ)*DKH;
    const __half* Vg = Vp + (size_t)((b*HEADS + h)*SEQ)*DKH;

    // 64 rows x 8 chunks(16B) = 512 chunks per tile; 4/thread
    int crow[4], coff[4];
#pragma unroll
    for (int l = 0; l < 4; l++) {
        int c = tid + l*128;
        crow[l] = c >> 3; coff[l] = (c & 7) * 8;
    }

    auto issue_kv = [&](int tile) {
        int buf = tile & 1, k0 = tile * 64;
        unsigned dk = smem_u32(Ks + buf*FTS);
        unsigned dv = smem_u32(Vs + buf*FTS);
#pragma unroll
        for (int l = 0; l < 4; l++) {
            cpa16(dk + (crow[l]*FLD + coff[l])*2, Kg + (size_t)(k0 + crow[l])*DKH + coff[l]);
            cpa16(dv + (crow[l]*FLD + coff[l])*2, Vg + (size_t)(k0 + crow[l])*DKH + coff[l]);
        }
    };
    {   // group 0: Q + tile 0
        unsigned dq = smem_u32(Qs);
#pragma unroll
        for (int l = 0; l < 4; l++)
            cpa16(dq + (crow[l]*FLD + coff[l])*2, Qg + (size_t)crow[l]*DKH + coff[l]);
        issue_kv(0); cpa_commit();
    }

    // ldmatrix per-thread address constants
    const int krow_c = ((lane >> 4) & 1) * 8 + (lane & 7);  // row within fn-pair (K, non-trans)
    const int kkh    = ((lane >> 3) & 1) * 8;               // k-half select (K)
    const int vrow_c = (lane & 7) + ((lane >> 3) & 1) * 8;  // row within 16-k block (V, trans)
    const int vcol_c = (lane >> 4) * 8;                     // col within fn-pair (V)

    // mask row pointers (advance by 64 per tile)
    const int* mp0 = mask + (size_t)(b*SEQ + q0 + qw + g)*SEQ + 2*t;
    const int* mp1 = mp0 + 8*SEQ;

    unsigned aq[4][4];
    float o[8][4] = {};
    float m_[2] = {-1e30f, -1e30f};
    float l_[2] = {0.f, 0.f};

    for (int i = 0; i < 32; i++) {
        cpa_wait0();
        __syncthreads();                 // tile i ready; all reads of other buf done
        if (i + 1 < 32) { issue_kv(i + 1); cpa_commit(); }

        if (i == 0) {   // Q frags -> registers (once)
#pragma unroll
            for (int ks = 0; ks < 4; ks++) {
                const int r = qw + g, k = ks*16;
                aq[ks][0] = *(const unsigned*)&Qs[r*FLD + k + 2*t];
                aq[ks][1] = *(const unsigned*)&Qs[(r+8)*FLD + k + 2*t];
                aq[ks][2] = *(const unsigned*)&Qs[r*FLD + k + 8 + 2*t];
                aq[ks][3] = *(const unsigned*)&Qs[(r+8)*FLD + k + 8 + 2*t];
            }
        }

        const __half* Kb = Ks + (i & 1)*FTS;
        const __half* Vb = Vs + (i & 1)*FTS;
        const unsigned kbase = smem_u32(Kb);
        const unsigned vbase = smem_u32(Vb);

        // S = Q K^T (Q carries log2e/sqrt(dk)); K frags via ldmatrix.x4
        float sc[8][4] = {};
#pragma unroll
        for (int ks = 0; ks < 4; ks++) {
            const int k = ks*16;
#pragma unroll
            for (int p = 0; p < 4; p++) {
                unsigned r0, r1, r2, r3;
                unsigned addr = kbase + ((p*16 + krow_c)*FLD + k + kkh)*2;
                ldmx4(r0, r1, r2, r3, addr);
                unsigned b0[2] = {r0, r1}, b1[2] = {r2, r3};
                mma16(sc[2*p],   aq[ks], b0);
                mma16(sc[2*p+1], aq[ks], b1);
            }
        }

        // mask (loaded after MMA: shorter live range, latency hidden by occupancy)
#pragma unroll
        for (int fn = 0; fn < 8; fn++) {
            int2 m0v = *(const int2*)(mp0 + fn*8);
            int2 m1v = *(const int2*)(mp1 + fn*8);
            if (m0v.x == 0) sc[fn][0] = -1e30f;
            if (m0v.y == 0) sc[fn][1] = -1e30f;
            if (m1v.x == 0) sc[fn][2] = -1e30f;
            if (m1v.y == 0) sc[fn][3] = -1e30f;
        }
        mp0 += 64; mp1 += 64;

        // online softmax in exp2 domain
#pragma unroll
        for (int rr = 0; rr < 2; rr++) {
            float rmax = -1e30f;
#pragma unroll
            for (int fn = 0; fn < 8; fn++)
                rmax = fmaxf(rmax, fmaxf(sc[fn][rr*2], sc[fn][rr*2+1]));
            rmax = fmaxf(rmax, __shfl_xor_sync(0xffffffffu, rmax, 1));
            rmax = fmaxf(rmax, __shfl_xor_sync(0xffffffffu, rmax, 2));
            float mn = fmaxf(m_[rr], rmax);
            float alpha = exp2f(m_[rr] - mn);
            float rsum = 0.f;
#pragma unroll
            for (int fn = 0; fn < 8; fn++) {
                sc[fn][rr*2]   = exp2f(sc[fn][rr*2]   - mn);
                sc[fn][rr*2+1] = exp2f(sc[fn][rr*2+1] - mn);
                rsum += sc[fn][rr*2] + sc[fn][rr*2+1];
            }
            rsum += __shfl_xor_sync(0xffffffffu, rsum, 1);
            rsum += __shfl_xor_sync(0xffffffffu, rsum, 2);
            l_[rr] = l_[rr]*alpha + rsum;
            m_[rr] = mn;
#pragma unroll
            for (int fn = 0; fn < 8; fn++) { o[fn][rr*2] *= alpha; o[fn][rr*2+1] *= alpha; }
        }

        // O += P @ V — P stays in registers: S C-frag layout == PV A-frag layout
#pragma unroll
        for (int ks = 0; ks < 4; ks++) {
            const int k = ks*16;
            unsigned ap[4];
            ap[0] = packh2(sc[2*ks][0],   sc[2*ks][1]);
            ap[1] = packh2(sc[2*ks][2],   sc[2*ks][3]);
            ap[2] = packh2(sc[2*ks+1][0], sc[2*ks+1][1]);
            ap[3] = packh2(sc[2*ks+1][2], sc[2*ks+1][3]);
#pragma unroll
            for (int fp = 0; fp < 4; fp++) {
                unsigned r0, r1, r2, r3;
                unsigned addr = vbase + ((k + vrow_c)*FLD + fp*16 + vcol_c)*2;
                ldmx4t(r0, r1, r2, r3, addr);
                unsigned b0[2] = {r0, r1}, b1[2] = {r2, r3};
                mma16(o[2*fp],   ap, b0);
                mma16(o[2*fp+1], ap, b1);
            }
        }
    }

    // normalize + half store, merged [B,S, h*64+d]
#pragma unroll
    for (int rr = 0; rr < 2; rr++) {
        float inv = 1.0f / l_[rr];
        int row = q0 + qw + g + rr*8;
        __half* op = Out + (size_t)(b*SEQ + row)*DMODEL + h*DKH + 2*t;
#pragma unroll
        for (int fn = 0; fn < 8; fn++)
            *(half2*)(op + fn*8) = __floats2half2_rn(o[fn][rr*2]*inv, o[fn][rr*2+1]*inv);
    }
}

// ---------------------------------------------------------------------------
extern "C" void kernel_launch(void* const* d_in, const int* in_sizes, int n_in,
                              void* d_out, int out_size)
{
    const float* q  = (const float*)d_in[0];
    const float* k  = (const float*)d_in[1];
    const float* v  = (const float*)d_in[2];
    const int*   mk = (const int*)  d_in[3];
    const float* wq = (const float*)d_in[4];
    const float* wk = (const float*)d_in[5];
    const float* wv = (const float*)d_in[6];
    const float* wo = (const float*)d_in[7];
    const float* bo = (const float*)d_in[8];
    float* out = (float*)d_out;

    __half *qh, *kh, *vh, *wqh, *wkh, *wvh, *woh, *qp, *kp, *vp, *ao;
    cudaGetSymbolAddress((void**)&qh,  g_qh);
    cudaGetSymbolAddress((void**)&kh,  g_kh);
    cudaGetSymbolAddress((void**)&vh,  g_vh);
    cudaGetSymbolAddress((void**)&wqh, g_wqh);
    cudaGetSymbolAddress((void**)&wkh, g_wkh);
    cudaGetSymbolAddress((void**)&wvh, g_wvh);
    cudaGetSymbolAddress((void**)&woh, g_woh);
    cudaGetSymbolAddress((void**)&qp,  g_qp);
    cudaGetSymbolAddress((void**)&kp,  g_kp);
    cudaGetSymbolAddress((void**)&vp,  g_vp);
    cudaGetSymbolAddress((void**)&ao,  g_ao);

    const int gemm_smem  = 6 * 128 * GLD * 2;      // 61440 B
    const int flash_smem = 5 * FTS * 2;            // 46080 B
    cudaFuncSetAttribute(gemm_h,  cudaFuncAttributeMaxDynamicSharedMemorySize, gemm_smem);
    cudaFuncSetAttribute(flash_h, cudaFuncAttributeMaxDynamicSharedMemorySize, flash_smem);

    // fp32 -> fp16 conversions
    f2h4<<<dim3(512, 3), 256>>>(q, k, v, nullptr, qh, kh, vh, nullptr, MR*DMODEL/4);
    f2h4<<<dim3(128, 4), 256>>>(wq, wk, wv, wo, wqh, wkh, wvh, woh, DMODEL*DMODEL/4);

    // fused QKV projections; q scale = log2(e)/sqrt(64) for exp2-domain softmax
    GemmArgs pa;
    pa.A[0] = qh;  pa.A[1] = kh;  pa.A[2] = vh;
    pa.W[0] = wqh; pa.W[1] = wkh; pa.W[2] = wvh;
    pa.C[0] = qp;  pa.C[1] = kp;  pa.C[2] = vp;
    pa.scale[0] = 0.125f * 1.44269504088896f; pa.scale[1] = 1.0f; pa.scale[2] = 1.0f;
    pa.bias = nullptr; pa.split = 1;
    gemm_h<<<dim3(DMODEL/128, MR/128, 3), 256, gemm_smem>>>(pa);

    flash_h<<<dim3(SEQ/64, HEADS, BATCH), 128, flash_smem>>>(qp, kp, vp, mk, ao);

    // output projection + bias
    GemmArgs oa;
    oa.A[0] = ao; oa.A[1] = nullptr; oa.A[2] = nullptr;
    oa.W[0] = woh; oa.W[1] = nullptr; oa.W[2] = nullptr;
    oa.C[0] = out; oa.C[1] = nullptr; oa.C[2] = nullptr;
    oa.scale[0] = 1.0f; oa.scale[1] = 1.0f; oa.scale[2] = 1.0f;
    oa.bias = bo; oa.split = 0;
    gemm_h<<<dim3(DMODEL/128, MR/128, 1), 256, gemm_smem>>>(oa);
}

// round 9
// speedup vs baseline: 10.8405x; 1.0184x over previous
#include <cuda_runtime.h>
#include <cuda_fp16.h>

#define DMODEL 1024
#define HEADS  16
#define DKH    64
#define BATCH  2
#define SEQ    2048
#define MR     (BATCH*SEQ)   // 4096 rows

// --------------------------- device scratch (no allocs) ---------------------
__device__ __half g_qh[MR*DMODEL];   // half copies of inputs
__device__ __half g_kh[MR*DMODEL];
__device__ __half g_vh[MR*DMODEL];
__device__ __half g_wqh[DMODEL*DMODEL];
__device__ __half g_wkh[DMODEL*DMODEL];
__device__ __half g_wvh[DMODEL*DMODEL];
__device__ __half g_woh[DMODEL*DMODEL];
__device__ __half g_qp[MR*DMODEL];   // projected, head-split [B,H,S,DKH], q scaled by log2e/8
__device__ __half g_kp[MR*DMODEL];
__device__ __half g_vp[MR*DMODEL];
__device__ __half g_ao[MR*DMODEL];   // attention out, merged [B,S,H*DKH]

// --------------------------- helpers ----------------------------------------
__device__ __forceinline__ unsigned smem_u32(const void* p) {
    return (unsigned)__cvta_generic_to_shared(p);
}
__device__ __forceinline__ void cpa16(unsigned dst, const void* src) {
    asm volatile("cp.async.cg.shared.global [%0], [%1], 16;" :: "r"(dst), "l"(src));
}
__device__ __forceinline__ void cpa_commit() { asm volatile("cp.async.commit_group;"); }
__device__ __forceinline__ void cpa_wait0()  { asm volatile("cp.async.wait_group 0;"); }
__device__ __forceinline__ void cpa_wait1()  { asm volatile("cp.async.wait_group 1;"); }

// D(16x8) += A(16x16) * B(16x8), f16 in, f32 accum
__device__ __forceinline__ void mma16(float* c, const unsigned* a, const unsigned* b) {
    asm volatile("mma.sync.aligned.m16n8k16.row.col.f32.f16.f16.f32 "
        "{%0,%1,%2,%3}, {%4,%5,%6,%7}, {%8,%9}, {%0,%1,%2,%3};"
        : "+f"(c[0]), "+f"(c[1]), "+f"(c[2]), "+f"(c[3])
        : "r"(a[0]), "r"(a[1]), "r"(a[2]), "r"(a[3]), "r"(b[0]), "r"(b[1]));
}
__device__ __forceinline__ void ldmx4(unsigned& r0, unsigned& r1, unsigned& r2, unsigned& r3, unsigned a) {
    asm volatile("ldmatrix.sync.aligned.m8n8.x4.shared.b16 {%0,%1,%2,%3}, [%4];"
        : "=r"(r0), "=r"(r1), "=r"(r2), "=r"(r3) : "r"(a));
}
__device__ __forceinline__ void ldmx4t(unsigned& r0, unsigned& r1, unsigned& r2, unsigned& r3, unsigned a) {
    asm volatile("ldmatrix.sync.aligned.m8n8.x4.trans.shared.b16 {%0,%1,%2,%3}, [%4];"
        : "=r"(r0), "=r"(r1), "=r"(r2), "=r"(r3) : "r"(a));
}
__device__ __forceinline__ unsigned packh2(float a, float b) {
    half2 h = __floats2half2_rn(a, b);
    return *reinterpret_cast<unsigned*>(&h);
}

// --------------------------- fp32 -> fp16 converter --------------------------
__global__ void f2h4(const float* __restrict__ s0, const float* __restrict__ s1,
                     const float* __restrict__ s2, const float* __restrict__ s3,
                     __half* d0, __half* d1, __half* d2, __half* d3, int n4)
{
    const float* s; __half* d;
    switch (blockIdx.y) {
        case 0: s = s0; d = d0; break;
        case 1: s = s1; d = d1; break;
        case 2: s = s2; d = d2; break;
        default: s = s3; d = d3; break;
    }
    for (int i = blockIdx.x*blockDim.x + threadIdx.x; i < n4; i += gridDim.x*blockDim.x) {
        float4 v = ((const float4*)s)[i];
        ((half2*)d)[2*i]   = __floats2half2_rn(v.x, v.y);
        ((half2*)d)[2*i+1] = __floats2half2_rn(v.z, v.w);
    }
}

// ---------------------------------------------------------------------------
// C = scale * A @ W^T (+bias). z = blockIdx.z selects (A, W, C, scale).
// CTA 128x128, 256 threads / 8 warps (2m x 4n), warp tile 64x32, Kt=32,
// 3-stage cp.async pipeline.
// split=1: C half, head-split [B,H,S,DKH]; split=0: C float, +bias.
// ---------------------------------------------------------------------------
struct GemmArgs {
    const __half* A[3]; const __half* W[3]; void* C[3];
    float scale[3]; const float* bias; int split;
};

#define GLD 40   // smem row stride in halves (80B, conflict-free)
__global__ __launch_bounds__(256, 2) void gemm_h(GemmArgs ga)
{
    extern __shared__ __half sm[];
    __half* smA = sm;                 // 3 x [128][GLD]
    __half* smB = sm + 3*128*GLD;     // 3 x [128][GLD]

    const int tid = threadIdx.x, lane = tid & 31;
    const int g = lane >> 2, t = lane & 3, wid = tid >> 5;
    const int wm = (wid & 1) * 64, wn = (wid >> 1) * 32;
    const int m0 = blockIdx.y * 128, n0 = blockIdx.x * 128;
    const int z = blockIdx.z;

    const __half* Ag = ga.A[z] + (size_t)m0 * DMODEL;
    const __half* Wg = ga.W[z] + (size_t)n0 * DMODEL;
    const float scale = ga.scale[z];

    int crow[2], coff[2];
#pragma unroll
    for (int l = 0; l < 2; l++) {
        int c = tid + l*256;
        crow[l] = c >> 2; coff[l] = (c & 3) * 8;
    }

    auto issue = [&](int tile) {
        int buf = tile % 3, k0 = tile * 32;
        unsigned da = smem_u32(smA + buf*128*GLD);
        unsigned db = smem_u32(smB + buf*128*GLD);
#pragma unroll
        for (int l = 0; l < 2; l++) {
            cpa16(da + (crow[l]*GLD + coff[l])*2, Ag + (size_t)crow[l]*DMODEL + k0 + coff[l]);
            cpa16(db + (crow[l]*GLD + coff[l])*2, Wg + (size_t)crow[l]*DMODEL + k0 + coff[l]);
        }
    };
    issue(0); cpa_commit();
    issue(1); cpa_commit();

    float acc[4][4][4] = {};

    for (int i = 0; i < 32; i++) {
        cpa_wait1();
        __syncthreads();
        if (i + 2 < 32) issue(i + 2);
        cpa_commit();

        const __half* As = smA + (i % 3)*128*GLD;
        const __half* Bs = smB + (i % 3)*128*GLD;
#pragma unroll
        for (int ks = 0; ks < 2; ks++) {
            const int k = ks * 16;
            unsigned af[4][4], bf[4][2];
#pragma unroll
            for (int fm = 0; fm < 4; fm++) {
                int r = wm + fm*16 + g;
                af[fm][0] = *(const unsigned*)&As[r*GLD + k + 2*t];
                af[fm][1] = *(const unsigned*)&As[(r+8)*GLD + k + 2*t];
                af[fm][2] = *(const unsigned*)&As[r*GLD + k + 8 + 2*t];
                af[fm][3] = *(const unsigned*)&As[(r+8)*GLD + k + 8 + 2*t];
            }
#pragma unroll
            for (int fn = 0; fn < 4; fn++) {
                int c = wn + fn*8 + g;
                bf[fn][0] = *(const unsigned*)&Bs[c*GLD + k + 2*t];
                bf[fn][1] = *(const unsigned*)&Bs[c*GLD + k + 8 + 2*t];
            }
#pragma unroll
            for (int fm = 0; fm < 4; fm++)
#pragma unroll
                for (int fn = 0; fn < 4; fn++) mma16(acc[fm][fn], af[fm], bf[fn]);
        }
        __syncthreads();
    }

#pragma unroll
    for (int fn = 0; fn < 4; fn++) {
        int n = n0 + wn + fn*8 + 2*t;
        float b0 = 0.f, b1 = 0.f;
        if (ga.bias) { b0 = ga.bias[n]; b1 = ga.bias[n+1]; }
#pragma unroll
        for (int fm = 0; fm < 4; fm++) {
#pragma unroll
            for (int rr = 0; rr < 2; rr++) {
                int m = m0 + wm + fm*16 + g + rr*8;
                float vx = acc[fm][fn][rr*2]   * scale + b0;
                float vy = acc[fm][fn][rr*2+1] * scale + b1;
                if (ga.split) {
                    int bb = m >> 11, ss = m & (SEQ-1);
                    int hh = n >> 6,  dd = n & 63;
                    __half* C = (__half*)ga.C[z];
                    *(half2*)(C + (size_t)(((bb*HEADS + hh)*SEQ) + ss)*DKH + dd) =
                        __floats2half2_rn(vx, vy);
                } else {
                    float* C = (float*)ga.C[z];
                    *(float2*)(C + (size_t)m*DMODEL + n) = make_float2(vx, vy);
                }
            }
        }
    }
}

// ---------------------------------------------------------------------------
// Flash attention fp16, exp2-domain softmax. Br=128 (4 warps x 32 q-rows,
// 2 row-fragments per warp), Bc=64, 2-stage cp.async K/V pipeline.
// Each K/V ldmatrix.x4 feeds 4 MMAs (2 row-frags) -> half the smem traffic
// per MMA vs 16-row warps. Q-frags register-resident; P in registers.
// ---------------------------------------------------------------------------
#define FLD 72   // smem row stride in halves (144B)
#define FTS (64*FLD)
__global__ __launch_bounds__(128, 2) void flash_h(
    const __half* __restrict__ Qp, const __half* __restrict__ Kp,
    const __half* __restrict__ Vp, const int* __restrict__ mask,
    __half* __restrict__ Out)
{
    extern __shared__ __half fsm[];
    __half* Qs = fsm;                 // [128][FLD]
    __half* Ks = fsm + 2*FTS;         // 2 x [64][FLD]
    __half* Vs = fsm + 4*FTS;         // 2 x [64][FLD]

    const int tid = threadIdx.x, lane = tid & 31;
    const int g = lane >> 2, t = lane & 3, wid = tid >> 5;
    const int q0 = blockIdx.x * 128, h = blockIdx.y, b = blockIdx.z;
    const int qw = wid * 32;

    const __half* Qg = Qp + (size_t)((b*HEADS + h)*SEQ + q0)*DKH;
    const __half* Kg = Kp + (size_t)((b*HEADS + h)*SEQ)*DKH;
    const __half* Vg = Vp + (size_t)((b*HEADS + h)*SEQ)*DKH;

    // K/V tile: 64 rows x 8 chunks(16B) = 512 chunks; 4/thread
    int crow[4], coff[4];
#pragma unroll
    for (int l = 0; l < 4; l++) {
        int c = tid + l*128;
        crow[l] = c >> 3; coff[l] = (c & 7) * 8;
    }

    auto issue_kv = [&](int tile) {
        int buf = tile & 1, k0 = tile * 64;
        unsigned dk = smem_u32(Ks + buf*FTS);
        unsigned dv = smem_u32(Vs + buf*FTS);
#pragma unroll
        for (int l = 0; l < 4; l++) {
            cpa16(dk + (crow[l]*FLD + coff[l])*2, Kg + (size_t)(k0 + crow[l])*DKH + coff[l]);
            cpa16(dv + (crow[l]*FLD + coff[l])*2, Vg + (size_t)(k0 + crow[l])*DKH + coff[l]);
        }
    };
    {   // group 0: Q (128 rows = 1024 chunks, 8/thread) + K/V tile 0
        unsigned dq = smem_u32(Qs);
#pragma unroll
        for (int l = 0; l < 8; l++) {
            int c = tid + l*128;
            int r = c >> 3, cc = (c & 7) * 8;
            cpa16(dq + (r*FLD + cc)*2, Qg + (size_t)r*DKH + cc);
        }
        issue_kv(0); cpa_commit();
    }

    // ldmatrix per-thread address constants
    const int krow_c = ((lane >> 4) & 1) * 8 + (lane & 7);  // K, non-trans
    const int kkh    = ((lane >> 3) & 1) * 8;
    const int vrow_c = (lane & 7) + ((lane >> 3) & 1) * 8;  // V, trans
    const int vcol_c = (lane >> 4) * 8;

    // mask row pointers: [rb][rr] -> row qw + rb*16 + rr*8 + g
    const int* mp[2][2];
#pragma unroll
    for (int rb = 0; rb < 2; rb++)
#pragma unroll
        for (int rr = 0; rr < 2; rr++)
            mp[rb][rr] = mask + (size_t)(b*SEQ + q0 + qw + rb*16 + rr*8 + g)*SEQ + 2*t;

    unsigned aq[2][4][4];
    float o[2][8][4] = {};
    float m_[2][2] = {{-1e30f,-1e30f},{-1e30f,-1e30f}};
    float l_[2][2] = {{0.f,0.f},{0.f,0.f}};

    for (int i = 0; i < 32; i++) {
        cpa_wait0();
        __syncthreads();                 // tile i ready; all reads of other buf done
        if (i + 1 < 32) { issue_kv(i + 1); cpa_commit(); }

        if (i == 0) {   // Q frags -> registers (once)
#pragma unroll
            for (int rb = 0; rb < 2; rb++)
#pragma unroll
                for (int ks = 0; ks < 4; ks++) {
                    const int r = qw + rb*16 + g, k = ks*16;
                    aq[rb][ks][0] = *(const unsigned*)&Qs[r*FLD + k + 2*t];
                    aq[rb][ks][1] = *(const unsigned*)&Qs[(r+8)*FLD + k + 2*t];
                    aq[rb][ks][2] = *(const unsigned*)&Qs[r*FLD + k + 8 + 2*t];
                    aq[rb][ks][3] = *(const unsigned*)&Qs[(r+8)*FLD + k + 8 + 2*t];
                }
        }

        const unsigned kbase = smem_u32(Ks + (i & 1)*FTS);
        const unsigned vbase = smem_u32(Vs + (i & 1)*FTS);

        // S = Q K^T; each ldmatrix.x4 feeds 4 MMAs (2 row-frags x 2 cols)
        float sc[2][8][4] = {};
#pragma unroll
        for (int ks = 0; ks < 4; ks++) {
            const int k = ks*16;
#pragma unroll
            for (int p = 0; p < 4; p++) {
                unsigned r0, r1, r2, r3;
                unsigned addr = kbase + ((p*16 + krow_c)*FLD + k + kkh)*2;
                ldmx4(r0, r1, r2, r3, addr);
                unsigned b0[2] = {r0, r1}, b1[2] = {r2, r3};
#pragma unroll
                for (int rb = 0; rb < 2; rb++) {
                    mma16(sc[rb][2*p],   aq[rb][ks], b0);
                    mma16(sc[rb][2*p+1], aq[rb][ks], b1);
                }
            }
        }

        // mask
#pragma unroll
        for (int rb = 0; rb < 2; rb++)
#pragma unroll
            for (int fn = 0; fn < 8; fn++) {
                int2 m0v = *(const int2*)(mp[rb][0] + fn*8);
                int2 m1v = *(const int2*)(mp[rb][1] + fn*8);
                if (m0v.x == 0) sc[rb][fn][0] = -1e30f;
                if (m0v.y == 0) sc[rb][fn][1] = -1e30f;
                if (m1v.x == 0) sc[rb][fn][2] = -1e30f;
                if (m1v.y == 0) sc[rb][fn][3] = -1e30f;
            }
#pragma unroll
        for (int rb = 0; rb < 2; rb++)
#pragma unroll
            for (int rr = 0; rr < 2; rr++) mp[rb][rr] += 64;

        // online softmax (exp2 domain)
#pragma unroll
        for (int rb = 0; rb < 2; rb++)
#pragma unroll
            for (int rr = 0; rr < 2; rr++) {
                float rmax = -1e30f;
#pragma unroll
                for (int fn = 0; fn < 8; fn++)
                    rmax = fmaxf(rmax, fmaxf(sc[rb][fn][rr*2], sc[rb][fn][rr*2+1]));
                rmax = fmaxf(rmax, __shfl_xor_sync(0xffffffffu, rmax, 1));
                rmax = fmaxf(rmax, __shfl_xor_sync(0xffffffffu, rmax, 2));
                float mn = fmaxf(m_[rb][rr], rmax);
                float alpha = exp2f(m_[rb][rr] - mn);
                float rsum = 0.f;
#pragma unroll
                for (int fn = 0; fn < 8; fn++) {
                    sc[rb][fn][rr*2]   = exp2f(sc[rb][fn][rr*2]   - mn);
                    sc[rb][fn][rr*2+1] = exp2f(sc[rb][fn][rr*2+1] - mn);
                    rsum += sc[rb][fn][rr*2] + sc[rb][fn][rr*2+1];
                }
                rsum += __shfl_xor_sync(0xffffffffu, rsum, 1);
                rsum += __shfl_xor_sync(0xffffffffu, rsum, 2);
                l_[rb][rr] = l_[rb][rr]*alpha + rsum;
                m_[rb][rr] = mn;
#pragma unroll
                for (int fn = 0; fn < 8; fn++) {
                    o[rb][fn][rr*2]   *= alpha;
                    o[rb][fn][rr*2+1] *= alpha;
                }
            }

        // O += P @ V; each ldmatrix.x4.trans feeds 4 MMAs
#pragma unroll
        for (int ks = 0; ks < 4; ks++) {
            const int k = ks*16;
            unsigned ap[2][4];
#pragma unroll
            for (int rb = 0; rb < 2; rb++) {
                ap[rb][0] = packh2(sc[rb][2*ks][0],   sc[rb][2*ks][1]);
                ap[rb][1] = packh2(sc[rb][2*ks][2],   sc[rb][2*ks][3]);
                ap[rb][2] = packh2(sc[rb][2*ks+1][0], sc[rb][2*ks+1][1]);
                ap[rb][3] = packh2(sc[rb][2*ks+1][2], sc[rb][2*ks+1][3]);
            }
#pragma unroll
            for (int fp = 0; fp < 4; fp++) {
                unsigned r0, r1, r2, r3;
                unsigned addr = vbase + ((k + vrow_c)*FLD + fp*16 + vcol_c)*2;
                ldmx4t(r0, r1, r2, r3, addr);
                unsigned b0[2] = {r0, r1}, b1[2] = {r2, r3};
#pragma unroll
                for (int rb = 0; rb < 2; rb++) {
                    mma16(o[rb][2*fp],   ap[rb], b0);
                    mma16(o[rb][2*fp+1], ap[rb], b1);
                }
            }
        }
    }

    // normalize + half store, merged [B,S, h*64+d]
#pragma unroll
    for (int rb = 0; rb < 2; rb++)
#pragma unroll
        for (int rr = 0; rr < 2; rr++) {
            float inv = 1.0f / l_[rb][rr];
            int row = q0 + qw + rb*16 + rr*8 + g;
            __half* op = Out + (size_t)(b*SEQ + row)*DMODEL + h*DKH + 2*t;
#pragma unroll
            for (int fn = 0; fn < 8; fn++)
                *(half2*)(op + fn*8) =
                    __floats2half2_rn(o[rb][fn][rr*2]*inv, o[rb][fn][rr*2+1]*inv);
        }
}

// ---------------------------------------------------------------------------
extern "C" void kernel_launch(void* const* d_in, const int* in_sizes, int n_in,
                              void* d_out, int out_size)
{
    const float* q  = (const float*)d_in[0];
    const float* k  = (const float*)d_in[1];
    const float* v  = (const float*)d_in[2];
    const int*   mk = (const int*)  d_in[3];
    const float* wq = (const float*)d_in[4];
    const float* wk = (const float*)d_in[5];
    const float* wv = (const float*)d_in[6];
    const float* wo = (const float*)d_in[7];
    const float* bo = (const float*)d_in[8];
    float* out = (float*)d_out;

    __half *qh, *kh, *vh, *wqh, *wkh, *wvh, *woh, *qp, *kp, *vp, *ao;
    cudaGetSymbolAddress((void**)&qh,  g_qh);
    cudaGetSymbolAddress((void**)&kh,  g_kh);
    cudaGetSymbolAddress((void**)&vh,  g_vh);
    cudaGetSymbolAddress((void**)&wqh, g_wqh);
    cudaGetSymbolAddress((void**)&wkh, g_wkh);
    cudaGetSymbolAddress((void**)&wvh, g_wvh);
    cudaGetSymbolAddress((void**)&woh, g_woh);
    cudaGetSymbolAddress((void**)&qp,  g_qp);
    cudaGetSymbolAddress((void**)&kp,  g_kp);
    cudaGetSymbolAddress((void**)&vp,  g_vp);
    cudaGetSymbolAddress((void**)&ao,  g_ao);

    const int gemm_smem  = 6 * 128 * GLD * 2;      // 61440 B
    const int flash_smem = 6 * FTS * 2;            // 55296 B (Q 2 tiles + K/V 4)
    cudaFuncSetAttribute(gemm_h,  cudaFuncAttributeMaxDynamicSharedMemorySize, gemm_smem);
    cudaFuncSetAttribute(flash_h, cudaFuncAttributeMaxDynamicSharedMemorySize, flash_smem);

    // fp32 -> fp16 conversions
    f2h4<<<dim3(512, 3), 256>>>(q, k, v, nullptr, qh, kh, vh, nullptr, MR*DMODEL/4);
    f2h4<<<dim3(128, 4), 256>>>(wq, wk, wv, wo, wqh, wkh, wvh, woh, DMODEL*DMODEL/4);

    // fused QKV projections; q scale = log2(e)/sqrt(64) for exp2-domain softmax
    GemmArgs pa;
    pa.A[0] = qh;  pa.A[1] = kh;  pa.A[2] = vh;
    pa.W[0] = wqh; pa.W[1] = wkh; pa.W[2] = wvh;
    pa.C[0] = qp;  pa.C[1] = kp;  pa.C[2] = vp;
    pa.scale[0] = 0.125f * 1.44269504088896f; pa.scale[1] = 1.0f; pa.scale[2] = 1.0f;
    pa.bias = nullptr; pa.split = 1;
    gemm_h<<<dim3(DMODEL/128, MR/128, 3), 256, gemm_smem>>>(pa);

    flash_h<<<dim3(SEQ/128, HEADS, BATCH), 128, flash_smem>>>(qp, kp, vp, mk, ao);

    // output projection + bias
    GemmArgs oa;
    oa.A[0] = ao; oa.A[1] = nullptr; oa.A[2] = nullptr;
    oa.W[0] = woh; oa.W[1] = nullptr; oa.W[2] = nullptr;
    oa.C[0] = out; oa.C[1] = nullptr; oa.C[2] = nullptr;
    oa.scale[0] = 1.0f; oa.scale[1] = 1.0f; oa.scale[2] = 1.0f;
    oa.bias = bo; oa.split = 0;
    gemm_h<<<dim3(DMODEL/128, MR/128, 1), 256, gemm_smem>>>(oa);
}